// round 1
// baseline (speedup 1.0000x reference)
#include <cuda_runtime.h>
#include <cstdint>

// Problem constants
#define B_  32
#define T_  256
#define C_  2048
#define H_  16
#define D_  128
#define M_TOT (B_*T_)     // 8192

// Scratch (device globals; no runtime allocation)
__device__ float g_q[(size_t)B_*H_*T_*D_];
__device__ float g_k[(size_t)B_*H_*T_*D_];
__device__ float g_v[(size_t)B_*H_*T_*D_];
__device__ float g_y[(size_t)B_*T_*C_];
__device__ float g_cos[T_*64];
__device__ float g_sin[T_*64];

// ------------------------------------------------------------------
// GEMM: C[m][n] = sum_k A[m][k] * W[n][k]   (A: M x K row-major, W: N x K row-major)
// 128x128 tile, BK=16, 256 threads, 8x8 per-thread tile, double-buffered smem.
// mode 0: A = g_y, writes plain [M, N] to Cout (final output projection)
// mode 1: A = Aparam (x), writes transposed [B,H,T,D] to g_q/g_k/g_v by blockIdx.z
// ------------------------------------------------------------------
#define GBM 128
#define GBN 128
#define GBK 16
#define GPITCH 132

__global__ __launch_bounds__(256)
void gemm128(const float* __restrict__ Aparam,
             const float* __restrict__ W0, const float* __restrict__ W1,
             const float* __restrict__ W2,
             float* __restrict__ Cout,
             int K, int mode)
{
    const float* A = (mode == 0) ? g_y : Aparam;
    const float* W = (blockIdx.z == 0) ? W0 : (blockIdx.z == 1) ? W1 : W2;
    float* Cc;
    if (mode == 0) Cc = Cout;
    else Cc = (blockIdx.z == 0) ? g_q : (blockIdx.z == 1) ? g_k : g_v;

    __shared__ float As[2][GBK][GPITCH];
    __shared__ float Bs[2][GBK][GPITCH];

    const int tid = threadIdx.x;
    const int bm = blockIdx.y * GBM;
    const int bn = blockIdx.x * GBN;
    const int tx = tid & 15, ty = tid >> 4;

    // Tile-load mapping: 512 float4 per tile per matrix, 2 per thread.
    const int ar0 = tid >> 2;                 // rows 0..63
    const int ar1 = (tid >> 2) + 64;          // rows 64..127
    const int ac  = (tid & 3) * 4;            // col within BK

    const float* Aptr = A + (size_t)bm * K;
    const float* Wptr = W + (size_t)bn * K;

    float4 la0, la1, lb0, lb1;

    la0 = *(const float4*)(Aptr + (size_t)ar0 * K + ac);
    la1 = *(const float4*)(Aptr + (size_t)ar1 * K + ac);
    lb0 = *(const float4*)(Wptr + (size_t)ar0 * K + ac);
    lb1 = *(const float4*)(Wptr + (size_t)ar1 * K + ac);

    As[0][ac+0][ar0] = la0.x; As[0][ac+1][ar0] = la0.y;
    As[0][ac+2][ar0] = la0.z; As[0][ac+3][ar0] = la0.w;
    As[0][ac+0][ar1] = la1.x; As[0][ac+1][ar1] = la1.y;
    As[0][ac+2][ar1] = la1.z; As[0][ac+3][ar1] = la1.w;
    Bs[0][ac+0][ar0] = lb0.x; Bs[0][ac+1][ar0] = lb0.y;
    Bs[0][ac+2][ar0] = lb0.z; Bs[0][ac+3][ar0] = lb0.w;
    Bs[0][ac+0][ar1] = lb1.x; Bs[0][ac+1][ar1] = lb1.y;
    Bs[0][ac+2][ar1] = lb1.z; Bs[0][ac+3][ar1] = lb1.w;

    float acc[8][8];
    #pragma unroll
    for (int i = 0; i < 8; i++)
        #pragma unroll
        for (int j = 0; j < 8; j++) acc[i][j] = 0.0f;

    __syncthreads();

    const int nkt = K / GBK;
    for (int kt = 0; kt < nkt; kt++) {
        const int buf = kt & 1;
        if (kt + 1 < nkt) {
            const int k0 = (kt + 1) * GBK;
            la0 = *(const float4*)(Aptr + (size_t)ar0 * K + k0 + ac);
            la1 = *(const float4*)(Aptr + (size_t)ar1 * K + k0 + ac);
            lb0 = *(const float4*)(Wptr + (size_t)ar0 * K + k0 + ac);
            lb1 = *(const float4*)(Wptr + (size_t)ar1 * K + k0 + ac);
        }
        #pragma unroll
        for (int k = 0; k < GBK; k++) {
            float4 a0 = *(const float4*)&As[buf][k][ty*4];
            float4 a1 = *(const float4*)&As[buf][k][64 + ty*4];
            float4 b0 = *(const float4*)&Bs[buf][k][tx*4];
            float4 b1 = *(const float4*)&Bs[buf][k][64 + tx*4];
            float av[8] = {a0.x, a0.y, a0.z, a0.w, a1.x, a1.y, a1.z, a1.w};
            float bv[8] = {b0.x, b0.y, b0.z, b0.w, b1.x, b1.y, b1.z, b1.w};
            #pragma unroll
            for (int i = 0; i < 8; i++)
                #pragma unroll
                for (int j = 0; j < 8; j++)
                    acc[i][j] = fmaf(av[i], bv[j], acc[i][j]);
        }
        if (kt + 1 < nkt) {
            const int nb = buf ^ 1;
            As[nb][ac+0][ar0] = la0.x; As[nb][ac+1][ar0] = la0.y;
            As[nb][ac+2][ar0] = la0.z; As[nb][ac+3][ar0] = la0.w;
            As[nb][ac+0][ar1] = la1.x; As[nb][ac+1][ar1] = la1.y;
            As[nb][ac+2][ar1] = la1.z; As[nb][ac+3][ar1] = la1.w;
            Bs[nb][ac+0][ar0] = lb0.x; Bs[nb][ac+1][ar0] = lb0.y;
            Bs[nb][ac+2][ar0] = lb0.z; Bs[nb][ac+3][ar0] = lb0.w;
            Bs[nb][ac+0][ar1] = lb1.x; Bs[nb][ac+1][ar1] = lb1.y;
            Bs[nb][ac+2][ar1] = lb1.z; Bs[nb][ac+3][ar1] = lb1.w;
            __syncthreads();
        }
    }

    // Epilogue
    #pragma unroll
    for (int i = 0; i < 8; i++) {
        const int mrow = bm + ((i < 4) ? (ty*4 + i) : (64 + ty*4 + i - 4));
        #pragma unroll
        for (int jg = 0; jg < 2; jg++) {
            const int n0 = bn + (jg ? 64 : 0) + tx*4;
            float4 val;
            val.x = acc[i][jg*4 + 0]; val.y = acc[i][jg*4 + 1];
            val.z = acc[i][jg*4 + 2]; val.w = acc[i][jg*4 + 3];
            if (mode == 0) {
                *(float4*)(Cc + (size_t)mrow * C_ + n0) = val;
            } else {
                const int b = mrow >> 8, t = mrow & 255;
                const int h = n0 >> 7, d = n0 & 127;
                *(float4*)(Cc + ((((size_t)b * H_ + h) * T_ + t) * D_ + d)) = val;
            }
        }
    }
}

// ------------------------------------------------------------------
// RoPE tables (double-precision trig, tiny kernel) + application
// ------------------------------------------------------------------
__global__ void rope_table_kernel()
{
    int idx = blockIdx.x * blockDim.x + threadIdx.x;  // T_*64 = 16384
    if (idx >= T_ * 64) return;
    int j = idx & 63;
    int t = idx >> 6;
    // inv_freq = 10000^(-j/64)
    double inv = exp(-(double)j * (9.210340371976184 / 64.0));
    double th = (double)t * inv;
    g_cos[idx] = (float)cos(th);
    g_sin[idx] = (float)sin(th);
}

__global__ __launch_bounds__(256)
void rope_kernel()
{
    int idx = blockIdx.x * 256 + threadIdx.x;   // 2 * 512 * 256 * 64
    int j = idx & 63;
    int t = (idx >> 6) & 255;
    int rest = idx >> 14;                        // 0..1023
    float* base = (rest & 512) ? g_k : g_q;
    int bh = rest & 511;
    float c = g_cos[t * 64 + j];
    float s = g_sin[t * 64 + j];
    float* p = base + (((size_t)bh * T_ + t) * D_) + j;
    float x0 = p[0], x1 = p[64];
    p[0]  = x0 * c - x1 * s;
    p[64] = x1 * c + x0 * s;
}

// ------------------------------------------------------------------
// Attention: block = (qtile of 32 queries) x (one b,h). 256 threads.
// Scores in registers, warp softmax, K/V streamed in 64-key smem tiles.
// Causal tile skipping: only ktiles with base <= qmax are processed.
// ------------------------------------------------------------------
#define ATTN_SMEM_FLOATS (32*128 + 32*257 + 64*129)

__global__ __launch_bounds__(256)
void attn_kernel()
{
    extern __shared__ float sm[];
    float* Qs  = sm;               // [32][128]
    float* Ps  = sm + 32*128;      // [32][257]
    float* KVs = Ps + 32*257;      // [64][129]

    const int qt  = blockIdx.x;    // 0..7
    const int bh  = blockIdx.y;    // 0..511
    const int tid = threadIdx.x;
    const int ty = tid >> 5, tx = tid & 31;

    const float* qb = g_q + ((size_t)bh * T_ + qt * 32) * D_;
    const float* kb = g_k + (size_t)bh * T_ * D_;
    const float* vb = g_v + (size_t)bh * T_ * D_;

    for (int i = tid; i < 32 * 128; i += 256) Qs[i] = qb[i];

    const float NEG_INF = __int_as_float(0xff800000);
    float s[4][8];
    #pragma unroll
    for (int i = 0; i < 4; i++)
        #pragma unroll
        for (int j = 0; j < 8; j++) s[i][j] = NEG_INF;

    const int nkt = (qt >> 1) + 1;
    const float SCALE = 0.08838834764831845f;  // 1/sqrt(128)

    __syncthreads();

    // Phase 1: scores
    for (int kt = 0; kt < nkt; kt++) {
        if (kt) __syncthreads();
        for (int i2 = tid; i2 < 64 * 128; i2 += 256) {
            int r = i2 >> 7, c = i2 & 127;
            KVs[r * 129 + c] = kb[((size_t)kt * 64 + r) * D_ + c];
        }
        __syncthreads();
        #pragma unroll
        for (int jl = 0; jl < 2; jl++) {
            const int lk = tx + 32 * jl;
            const float* kr = &KVs[lk * 129];
            const float* q0 = &Qs[(ty*4 + 0) * 128];
            const float* q1 = q0 + 128;
            const float* q2 = q0 + 256;
            const float* q3 = q0 + 384;
            float a0 = 0.f, a1 = 0.f, a2 = 0.f, a3 = 0.f;
            #pragma unroll 8
            for (int d = 0; d < 128; d++) {
                float kv = kr[d];
                a0 = fmaf(q0[d], kv, a0);
                a1 = fmaf(q1[d], kv, a1);
                a2 = fmaf(q2[d], kv, a2);
                a3 = fmaf(q3[d], kv, a3);
            }
            const int jj = kt * 2 + jl;
            s[0][jj] = a0 * SCALE;
            s[1][jj] = a1 * SCALE;
            s[2][jj] = a2 * SCALE;
            s[3][jj] = a3 * SCALE;
        }
    }

    // Causal mask: key = jj*32 + tx ; query = qt*32 + ty*4 + i
    const int q0g = qt * 32 + ty * 4;
    #pragma unroll
    for (int i = 0; i < 4; i++)
        #pragma unroll
        for (int jj = 0; jj < 8; jj++)
            if (jj * 32 + tx > q0g + i) s[i][jj] = NEG_INF;

    // Softmax per row (row spans the warp: 8 regs x 32 lanes)
    #pragma unroll
    for (int i = 0; i < 4; i++) {
        float m = NEG_INF;
        #pragma unroll
        for (int jj = 0; jj < 8; jj++) m = fmaxf(m, s[i][jj]);
        #pragma unroll
        for (int o = 16; o > 0; o >>= 1) m = fmaxf(m, __shfl_xor_sync(0xffffffffu, m, o));
        float sum = 0.f;
        #pragma unroll
        for (int jj = 0; jj < 8; jj++) {
            float e = __expf(s[i][jj] - m);
            s[i][jj] = e;
            sum += e;
        }
        #pragma unroll
        for (int o = 16; o > 0; o >>= 1) sum += __shfl_xor_sync(0xffffffffu, sum, o);
        const float inv = 1.0f / sum;
        #pragma unroll
        for (int jj = 0; jj < 8; jj++)
            Ps[(ty*4 + i) * 257 + jj * 32 + tx] = s[i][jj] * inv;
    }
    __syncwarp();

    // Phase 3: y = P @ V
    float ya[4][4];
    #pragma unroll
    for (int i = 0; i < 4; i++)
        #pragma unroll
        for (int j = 0; j < 4; j++) ya[i][j] = 0.0f;

    for (int kt = 0; kt < nkt; kt++) {
        __syncthreads();
        for (int i2 = tid; i2 < 64 * 128; i2 += 256) {
            int r = i2 >> 7, c = i2 & 127;
            KVs[r * 129 + c] = vb[((size_t)kt * 64 + r) * D_ + c];
        }
        __syncthreads();
        #pragma unroll 4
        for (int kk = 0; kk < 64; kk++) {
            const float vv0 = KVs[kk * 129 + tx];
            const float vv1 = KVs[kk * 129 + tx + 32];
            const float vv2 = KVs[kk * 129 + tx + 64];
            const float vv3 = KVs[kk * 129 + tx + 96];
            #pragma unroll
            for (int i = 0; i < 4; i++) {
                const float p = Ps[(ty*4 + i) * 257 + kt * 64 + kk];
                ya[i][0] = fmaf(p, vv0, ya[i][0]);
                ya[i][1] = fmaf(p, vv1, ya[i][1]);
                ya[i][2] = fmaf(p, vv2, ya[i][2]);
                ya[i][3] = fmaf(p, vv3, ya[i][3]);
            }
        }
    }

    // Write y in [B, T, C] layout
    const int b = bh >> 4, h = bh & 15;
    #pragma unroll
    for (int i = 0; i < 4; i++) {
        const size_t row = ((size_t)b * T_ + qt * 32 + ty * 4 + i) * C_ + h * D_ + tx;
        g_y[row]      = ya[i][0];
        g_y[row + 32] = ya[i][1];
        g_y[row + 64] = ya[i][2];
        g_y[row + 96] = ya[i][3];
    }
}

// ------------------------------------------------------------------
extern "C" void kernel_launch(void* const* d_in, const int* in_sizes, int n_in,
                              void* d_out, int out_size)
{
    const float* x  = (const float*)d_in[0];
    const float* wq = (const float*)d_in[1];
    const float* wk = (const float*)d_in[2];
    const float* wv = (const float*)d_in[3];
    const float* wo = (const float*)d_in[4];
    float* out = (float*)d_out;

    // QKV projections, fused via grid.z, epilogue writes [B,H,T,D]
    gemm128<<<dim3(C_/GBN, M_TOT/GBM, 3), 256>>>(x, wq, wk, wv, nullptr, C_, 1);

    // RoPE
    rope_table_kernel<<<(T_*64 + 255)/256, 256>>>();
    rope_kernel<<<(2 * 512 * 256 * 64) / 256, 256>>>();

    // Attention
    const int attn_smem = ATTN_SMEM_FLOATS * (int)sizeof(float);
    cudaFuncSetAttribute(attn_kernel, cudaFuncAttributeMaxDynamicSharedMemorySize, attn_smem);
    attn_kernel<<<dim3(8, 512), 256, attn_smem>>>();

    // Output projection: out = g_y @ wo^T
    gemm128<<<dim3(C_/GBN, M_TOT/GBM, 1), 256>>>(nullptr, wo, wo, wo, out, C_, 0);
}

// round 3
// speedup vs baseline: 2.2525x; 2.2525x over previous
#include <cuda_runtime.h>
#include <cuda_bf16.h>
#include <cstdint>

#define B_  32
#define T_  256
#define C_  2048
#define H_  16
#define D_  128
#define M_TOT (B_*T_)     // 8192

// ------------------------------------------------------------------
// Device globals (no runtime allocation allowed)
// ------------------------------------------------------------------
__device__ float g_q[(size_t)B_*H_*T_*D_];
__device__ float g_k[(size_t)B_*H_*T_*D_];
__device__ float g_v[(size_t)B_*H_*T_*D_];
__device__ float g_cos[T_*64];
__device__ float g_sin[T_*64];
__device__ __nv_bfloat16 g_xhi[(size_t)M_TOT*C_];
__device__ __nv_bfloat16 g_xlo[(size_t)M_TOT*C_];
__device__ __nv_bfloat16 g_whi[(size_t)4*C_*C_];
__device__ __nv_bfloat16 g_wlo[(size_t)4*C_*C_];
__device__ __nv_bfloat16 g_yhi[(size_t)M_TOT*C_];
__device__ __nv_bfloat16 g_ylo[(size_t)M_TOT*C_];

// ------------------------------------------------------------------
// PTX helpers
// ------------------------------------------------------------------
__device__ __forceinline__ uint32_t smem_u32(const void* p) {
    uint32_t a;
    asm("{ .reg .u64 t; cvta.to.shared.u64 t, %1; cvt.u32.u64 %0, t; }" : "=r"(a) : "l"(p));
    return a;
}
__device__ __forceinline__ void cp16(uint32_t dst, const void* src) {
    asm volatile("cp.async.cg.shared.global [%0], [%1], 16;" :: "r"(dst), "l"(src));
}
__device__ __forceinline__ void cp_commit() {
    asm volatile("cp.async.commit_group;" ::: "memory");
}
__device__ __forceinline__ void ldmx4(uint32_t* r, uint32_t addr) {
    asm volatile("ldmatrix.sync.aligned.m8n8.x4.shared.b16 {%0,%1,%2,%3}, [%4];"
                 : "=r"(r[0]), "=r"(r[1]), "=r"(r[2]), "=r"(r[3]) : "r"(addr));
}
__device__ __forceinline__ void mma16816(float* d, const uint32_t* a, const uint32_t* b) {
    asm volatile(
        "mma.sync.aligned.m16n8k16.row.col.f32.bf16.bf16.f32 "
        "{%0,%1,%2,%3}, {%4,%5,%6,%7}, {%8,%9}, {%0,%1,%2,%3};"
        : "+f"(d[0]), "+f"(d[1]), "+f"(d[2]), "+f"(d[3])
        : "r"(a[0]), "r"(a[1]), "r"(a[2]), "r"(a[3]), "r"(b[0]), "r"(b[1]));
}

// Swizzled smem offset within a [rows][32 bf16] tile (64B rows):
// phys = r*64 + ((c16 ^ ((r>>1)&3)) * 16), c16 = 16B-chunk index 0..3
__device__ __forceinline__ uint32_t swz(int r, int c) {
    return (uint32_t)(r * 64 + ((c ^ ((r >> 1) & 3)) << 4));
}

// ------------------------------------------------------------------
// fp32 -> bf16 hi/lo split
// ------------------------------------------------------------------
__global__ __launch_bounds__(256)
void split_kernel(const float4* __restrict__ src, int dst_sel, int n4)
{
    int i = blockIdx.x * 256 + threadIdx.x;
    if (i >= n4) return;
    __nv_bfloat16* hi;
    __nv_bfloat16* lo;
    if (dst_sel == 0)      { hi = g_xhi; lo = g_xlo; }
    else                   { hi = g_whi + (size_t)(dst_sel - 1) * C_ * C_;
                             lo = g_wlo + (size_t)(dst_sel - 1) * C_ * C_; }
    float4 v = src[i];
    __nv_bfloat16 h0 = __float2bfloat16(v.x);
    __nv_bfloat16 h1 = __float2bfloat16(v.y);
    __nv_bfloat16 h2 = __float2bfloat16(v.z);
    __nv_bfloat16 h3 = __float2bfloat16(v.w);
    __nv_bfloat16 l0 = __float2bfloat16(v.x - __bfloat162float(h0));
    __nv_bfloat16 l1 = __float2bfloat16(v.y - __bfloat162float(h1));
    __nv_bfloat16 l2 = __float2bfloat16(v.z - __bfloat162float(h2));
    __nv_bfloat16 l3 = __float2bfloat16(v.w - __bfloat162float(h3));
    __nv_bfloat162* hp = (__nv_bfloat162*)hi;
    __nv_bfloat162* lp = (__nv_bfloat162*)lo;
    hp[2*i]   = __halves2bfloat162(h0, h1);
    hp[2*i+1] = __halves2bfloat162(h2, h3);
    lp[2*i]   = __halves2bfloat162(l0, l1);
    lp[2*i+1] = __halves2bfloat162(l2, l3);
}

// ------------------------------------------------------------------
// HMMA GEMM: Cc[m][n] = sum_k A[m][k]*W[n][k], bf16-split (3 MMAs).
// CTA tile 128x128, BK=32, 4-stage cp.async pipeline, ldmatrix feeds.
// 8 warps: 4(M) x 2(N); warp tile 32(M) x 64(N).
// mode 1: A = g_xhi/lo, W = g_whi/lo[z] -> g_q/g_k/g_v in [B,H,T,D]
// mode 0: A = g_yhi/lo, W = g_whi/lo[3] -> Out [M, C]
// ------------------------------------------------------------------
#define STAGES 4
#define STAGE_BYTES 32768     // Ahi 8K | Alo 8K | Bhi 8K | Blo 8K
#define GEMM_SMEM (1024 + STAGES*STAGE_BYTES)

__global__ __launch_bounds__(256, 1)
void gemm_mma(float* __restrict__ Out, int mode)
{
    extern __shared__ char dsm[];
    const int tid  = threadIdx.x;
    const int wid  = tid >> 5;
    const int lane = tid & 31;
    const int bn = blockIdx.x * 128;
    const int bm = blockIdx.y * 128;
    const int wz = blockIdx.z;

    const __nv_bfloat16* Ahi_g = (mode == 0) ? g_yhi : g_xhi;
    const __nv_bfloat16* Alo_g = (mode == 0) ? g_ylo : g_xlo;
    const int widx = (mode == 0) ? 3 : wz;
    const __nv_bfloat16* Bhi_g = g_whi + (size_t)widx * C_ * C_;
    const __nv_bfloat16* Blo_g = g_wlo + (size_t)widx * C_ * C_;

    const uint32_t base = (smem_u32(dsm) + 1023u) & ~1023u;

    // per-thread load mapping: 2 chunk slots x 4 matrices
    const int j0 = tid;            // chunk ids j0, j0+256 of 512
    const int r0l = j0 >> 2,       c0l = j0 & 3;
    const int r1l = (j0 + 256) >> 2, c1l = (j0 + 256) & 3;
    const uint32_t ph0 = swz(r0l, c0l);
    const uint32_t ph1 = swz(r1l, c1l);

    auto load_stage = [&](int kt, int s) {
        const uint32_t sb = base + (uint32_t)s * STAGE_BYTES;
        const int kb = kt * 32;
        {
            const size_t ga = (size_t)(bm + r0l) * C_ + kb + c0l * 8;
            const size_t gb = (size_t)(bn + r0l) * C_ + kb + c0l * 8;
            cp16(sb + ph0,         Ahi_g + ga);
            cp16(sb + 8192  + ph0, Alo_g + ga);
            cp16(sb + 16384 + ph0, Bhi_g + gb);
            cp16(sb + 24576 + ph0, Blo_g + gb);
        }
        {
            const size_t ga = (size_t)(bm + r1l) * C_ + kb + c1l * 8;
            const size_t gb = (size_t)(bn + r1l) * C_ + kb + c1l * 8;
            cp16(sb + ph1,         Ahi_g + ga);
            cp16(sb + 8192  + ph1, Alo_g + ga);
            cp16(sb + 16384 + ph1, Bhi_g + gb);
            cp16(sb + 24576 + ph1, Blo_g + gb);
        }
        cp_commit();
    };

    // warp tiling
    const int wm = (wid >> 1) * 32;
    const int wn = (wid & 1) * 64;

    float acc[2][8][4];
    #pragma unroll
    for (int i = 0; i < 2; i++)
        #pragma unroll
        for (int j = 0; j < 8; j++)
            #pragma unroll
            for (int q = 0; q < 4; q++) acc[i][j][q] = 0.0f;

    // precompute ldmatrix address offsets (lane-dependent, stage-invariant)
    const int arow = wm + (lane & 15);                 // + mt*16
    const int acol_base = (lane >> 4);                 // + ks*2
    const int brow = wn + (lane & 7) + ((lane & 16) >> 1);  // + ng*16
    const int bcol_base = ((lane >> 3) & 1);           // + ks*2

    const int NK = C_ / 32;   // 64

    load_stage(0, 0);
    load_stage(1, 1);
    load_stage(2, 2);

    for (int c = 0; c < NK; c++) {
        __syncthreads();   // all warps finished computing slot being refilled
        if (c + 3 < NK) load_stage(c + 3, (c + 3) & 3);
        else            cp_commit();
        asm volatile("cp.async.wait_group 3;" ::: "memory");
        __syncthreads();   // publish stage c

        const uint32_t sA   = base + (uint32_t)(c & 3) * STAGE_BYTES;
        const uint32_t sAlo = sA + 8192;
        const uint32_t sB   = sA + 16384;
        const uint32_t sBlo = sA + 24576;

        #pragma unroll
        for (int ks = 0; ks < 2; ks++) {
            uint32_t ah[2][4], al[2][4];
            #pragma unroll
            for (int mt = 0; mt < 2; mt++) {
                const uint32_t ph = swz(arow + mt * 16, ks * 2 + acol_base);
                ldmx4(ah[mt], sA   + ph);
                ldmx4(al[mt], sAlo + ph);
            }
            uint32_t bh[8][2], bl[8][2];
            #pragma unroll
            for (int ng = 0; ng < 4; ng++) {
                const uint32_t ph = swz(brow + ng * 16, ks * 2 + bcol_base);
                uint32_t q[4];
                ldmx4(q, sB + ph);
                bh[2*ng][0] = q[0]; bh[2*ng][1] = q[1];
                bh[2*ng+1][0] = q[2]; bh[2*ng+1][1] = q[3];
                ldmx4(q, sBlo + ph);
                bl[2*ng][0] = q[0]; bl[2*ng][1] = q[1];
                bl[2*ng+1][0] = q[2]; bl[2*ng+1][1] = q[3];
            }
            #pragma unroll
            for (int mt = 0; mt < 2; mt++)
                #pragma unroll
                for (int nt = 0; nt < 8; nt++)
                    mma16816(acc[mt][nt], ah[mt], bh[nt]);
            #pragma unroll
            for (int mt = 0; mt < 2; mt++)
                #pragma unroll
                for (int nt = 0; nt < 8; nt++)
                    mma16816(acc[mt][nt], ah[mt], bl[nt]);
            #pragma unroll
            for (int mt = 0; mt < 2; mt++)
                #pragma unroll
                for (int nt = 0; nt < 8; nt++)
                    mma16816(acc[mt][nt], al[mt], bh[nt]);
        }
    }

    // Epilogue: direct float2 stores
    float* qkv = (wz == 0) ? g_q : (wz == 1) ? g_k : g_v;
    #pragma unroll
    for (int mt = 0; mt < 2; mt++) {
        const int row0 = bm + wm + mt * 16 + (lane >> 2);
        #pragma unroll
        for (int nt = 0; nt < 8; nt++) {
            const int col = bn + wn + nt * 8 + (lane & 3) * 2;
            #pragma unroll
            for (int half = 0; half < 2; half++) {
                const int row = row0 + half * 8;
                float2 v;
                v.x = acc[mt][nt][half * 2 + 0];
                v.y = acc[mt][nt][half * 2 + 1];
                if (mode == 0) {
                    *(float2*)(Out + (size_t)row * C_ + col) = v;
                } else {
                    const int b = row >> 8, t = row & 255;
                    const int h = col >> 7, d0 = col & 127;
                    *(float2*)(qkv + ((((size_t)b * H_ + h) * T_ + t) * D_ + d0)) = v;
                }
            }
        }
    }
}

// ------------------------------------------------------------------
// RoPE tables (double-precision trig) + application
// ------------------------------------------------------------------
__global__ void rope_table_kernel()
{
    int idx = blockIdx.x * blockDim.x + threadIdx.x;
    if (idx >= T_ * 64) return;
    int j = idx & 63;
    int t = idx >> 6;
    double inv = exp(-(double)j * (9.210340371976184 / 64.0));
    double th = (double)t * inv;
    g_cos[idx] = (float)cos(th);
    g_sin[idx] = (float)sin(th);
}

__global__ __launch_bounds__(256)
void rope_kernel()
{
    int idx = blockIdx.x * 256 + threadIdx.x;
    int j = idx & 63;
    int t = (idx >> 6) & 255;
    int rest = idx >> 14;
    float* basep = (rest & 512) ? g_k : g_q;
    int bh = rest & 511;
    float c = g_cos[t * 64 + j];
    float s = g_sin[t * 64 + j];
    float* p = basep + (((size_t)bh * T_ + t) * D_) + j;
    float x0 = p[0], x1 = p[64];
    p[0]  = x0 * c - x1 * s;
    p[64] = x1 * c + x0 * s;
}

// ------------------------------------------------------------------
// Attention (SIMT fp32; epilogue emits bf16 hi/lo y for out-proj)
// ------------------------------------------------------------------
#define ATTN_SMEM_FLOATS (32*128 + 32*257 + 64*129)

__global__ __launch_bounds__(256)
void attn_kernel()
{
    extern __shared__ float sm[];
    float* Qs  = sm;               // [32][128]
    float* Ps  = sm + 32*128;      // [32][257]
    float* KVs = Ps + 32*257;      // [64][129]

    const int qt  = blockIdx.x;
    const int bh  = blockIdx.y;
    const int tid = threadIdx.x;
    const int ty = tid >> 5, tx = tid & 31;

    const float* qb = g_q + ((size_t)bh * T_ + qt * 32) * D_;
    const float* kb = g_k + (size_t)bh * T_ * D_;
    const float* vb = g_v + (size_t)bh * T_ * D_;

    for (int i = tid; i < 32 * 128; i += 256) Qs[i] = qb[i];

    const float NEG_INF = __int_as_float(0xff800000);
    float s[4][8];
    #pragma unroll
    for (int i = 0; i < 4; i++)
        #pragma unroll
        for (int j = 0; j < 8; j++) s[i][j] = NEG_INF;

    const int nkt = (qt >> 1) + 1;
    const float SCALE = 0.08838834764831845f;

    __syncthreads();

    for (int kt = 0; kt < nkt; kt++) {
        if (kt) __syncthreads();
        for (int i2 = tid; i2 < 64 * 128; i2 += 256) {
            int r = i2 >> 7, c = i2 & 127;
            KVs[r * 129 + c] = kb[((size_t)kt * 64 + r) * D_ + c];
        }
        __syncthreads();
        #pragma unroll
        for (int jl = 0; jl < 2; jl++) {
            const int lk = tx + 32 * jl;
            const float* kr = &KVs[lk * 129];
            const float* q0 = &Qs[(ty*4 + 0) * 128];
            const float* q1 = q0 + 128;
            const float* q2 = q0 + 256;
            const float* q3 = q0 + 384;
            float a0 = 0.f, a1 = 0.f, a2 = 0.f, a3 = 0.f;
            #pragma unroll 8
            for (int d = 0; d < 128; d++) {
                float kv = kr[d];
                a0 = fmaf(q0[d], kv, a0);
                a1 = fmaf(q1[d], kv, a1);
                a2 = fmaf(q2[d], kv, a2);
                a3 = fmaf(q3[d], kv, a3);
            }
            const int jj = kt * 2 + jl;
            s[0][jj] = a0 * SCALE;
            s[1][jj] = a1 * SCALE;
            s[2][jj] = a2 * SCALE;
            s[3][jj] = a3 * SCALE;
        }
    }

    const int q0g = qt * 32 + ty * 4;
    #pragma unroll
    for (int i = 0; i < 4; i++)
        #pragma unroll
        for (int jj = 0; jj < 8; jj++)
            if (jj * 32 + tx > q0g + i) s[i][jj] = NEG_INF;

    #pragma unroll
    for (int i = 0; i < 4; i++) {
        float m = NEG_INF;
        #pragma unroll
        for (int jj = 0; jj < 8; jj++) m = fmaxf(m, s[i][jj]);
        #pragma unroll
        for (int o = 16; o > 0; o >>= 1) m = fmaxf(m, __shfl_xor_sync(0xffffffffu, m, o));
        float sum = 0.f;
        #pragma unroll
        for (int jj = 0; jj < 8; jj++) {
            float e = __expf(s[i][jj] - m);
            s[i][jj] = e;
            sum += e;
        }
        #pragma unroll
        for (int o = 16; o > 0; o >>= 1) sum += __shfl_xor_sync(0xffffffffu, sum, o);
        const float inv = 1.0f / sum;
        #pragma unroll
        for (int jj = 0; jj < 8; jj++)
            Ps[(ty*4 + i) * 257 + jj * 32 + tx] = s[i][jj] * inv;
    }
    __syncwarp();

    float ya[4][4];
    #pragma unroll
    for (int i = 0; i < 4; i++)
        #pragma unroll
        for (int j = 0; j < 4; j++) ya[i][j] = 0.0f;

    for (int kt = 0; kt < nkt; kt++) {
        __syncthreads();
        for (int i2 = tid; i2 < 64 * 128; i2 += 256) {
            int r = i2 >> 7, c = i2 & 127;
            KVs[r * 129 + c] = vb[((size_t)kt * 64 + r) * D_ + c];
        }
        __syncthreads();
        #pragma unroll 4
        for (int kk = 0; kk < 64; kk++) {
            const float vv0 = KVs[kk * 129 + tx];
            const float vv1 = KVs[kk * 129 + tx + 32];
            const float vv2 = KVs[kk * 129 + tx + 64];
            const float vv3 = KVs[kk * 129 + tx + 96];
            #pragma unroll
            for (int i = 0; i < 4; i++) {
                const float p = Ps[(ty*4 + i) * 257 + kt * 64 + kk];
                ya[i][0] = fmaf(p, vv0, ya[i][0]);
                ya[i][1] = fmaf(p, vv1, ya[i][1]);
                ya[i][2] = fmaf(p, vv2, ya[i][2]);
                ya[i][3] = fmaf(p, vv3, ya[i][3]);
            }
        }
    }

    const int b = bh >> 4, h = bh & 15;
    #pragma unroll
    for (int i = 0; i < 4; i++) {
        const size_t row = ((size_t)b * T_ + qt * 32 + ty * 4 + i) * C_ + h * D_ + tx;
        #pragma unroll
        for (int kq = 0; kq < 4; kq++) {
            float y = ya[i][kq];
            __nv_bfloat16 hh = __float2bfloat16(y);
            g_yhi[row + 32 * kq] = hh;
            g_ylo[row + 32 * kq] = __float2bfloat16(y - __bfloat162float(hh));
        }
    }
}

// ------------------------------------------------------------------
extern "C" void kernel_launch(void* const* d_in, const int* in_sizes, int n_in,
                              void* d_out, int out_size)
{
    const float* x  = (const float*)d_in[0];
    const float* wq = (const float*)d_in[1];
    const float* wk = (const float*)d_in[2];
    const float* wv = (const float*)d_in[3];
    const float* wo = (const float*)d_in[4];
    float* out = (float*)d_out;

    const int nx4 = M_TOT * C_ / 4;
    const int nw4 = C_ * C_ / 4;
    split_kernel<<<(nx4 + 255)/256, 256>>>((const float4*)x,  0, nx4);
    split_kernel<<<(nw4 + 255)/256, 256>>>((const float4*)wq, 1, nw4);
    split_kernel<<<(nw4 + 255)/256, 256>>>((const float4*)wk, 2, nw4);
    split_kernel<<<(nw4 + 255)/256, 256>>>((const float4*)wv, 3, nw4);
    split_kernel<<<(nw4 + 255)/256, 256>>>((const float4*)wo, 4, nw4);

    cudaFuncSetAttribute(gemm_mma, cudaFuncAttributeMaxDynamicSharedMemorySize, GEMM_SMEM);

    // QKV projections via HMMA, epilogue writes [B,H,T,D]
    gemm_mma<<<dim3(C_/128, M_TOT/128, 3), 256, GEMM_SMEM>>>(nullptr, 1);

    // RoPE
    rope_table_kernel<<<(T_*64 + 255)/256, 256>>>();
    rope_kernel<<<(2 * 512 * 256 * 64) / 256, 256>>>();

    // Attention
    const int attn_smem = ATTN_SMEM_FLOATS * (int)sizeof(float);
    cudaFuncSetAttribute(attn_kernel, cudaFuncAttributeMaxDynamicSharedMemorySize, attn_smem);
    attn_kernel<<<dim3(8, 512), 256, attn_smem>>>();

    // Output projection via HMMA
    gemm_mma<<<dim3(C_/128, M_TOT/128, 1), 256, GEMM_SMEM>>>(out, 0);
}

// round 4
// speedup vs baseline: 2.6541x; 1.1783x over previous
#include <cuda_runtime.h>
#include <cuda_bf16.h>
#include <cstdint>

#define B_  32
#define T_  256
#define C_  2048
#define H_  16
#define D_  128
#define M_TOT (B_*T_)     // 8192
#define BH_  (B_*H_)      // 512

// ------------------------------------------------------------------
// Device globals
// ------------------------------------------------------------------
__device__ float g_q[(size_t)BH_*T_*D_];        // fp32 Q pre-rope
__device__ float g_k[(size_t)BH_*T_*D_];        // fp32 K pre-rope
__device__ float g_cos[T_*64];
__device__ float g_sin[T_*64];
__device__ __nv_bfloat16 g_xhi[(size_t)M_TOT*C_];
__device__ __nv_bfloat16 g_xlo[(size_t)M_TOT*C_];
__device__ __nv_bfloat16 g_whi[(size_t)4*C_*C_];
__device__ __nv_bfloat16 g_wlo[(size_t)4*C_*C_];
__device__ __nv_bfloat16 g_yhi[(size_t)M_TOT*C_];
__device__ __nv_bfloat16 g_ylo[(size_t)M_TOT*C_];
__device__ __nv_bfloat16 g_qhi[(size_t)BH_*T_*D_];
__device__ __nv_bfloat16 g_qlo[(size_t)BH_*T_*D_];
__device__ __nv_bfloat16 g_khi[(size_t)BH_*T_*D_];
__device__ __nv_bfloat16 g_klo[(size_t)BH_*T_*D_];
__device__ __nv_bfloat16 g_vhi[(size_t)BH_*T_*D_];
__device__ __nv_bfloat16 g_vlo[(size_t)BH_*T_*D_];
__device__ float g_s[(size_t)BH_*T_*T_];        // 134MB scores
__device__ __nv_bfloat16 g_phi[(size_t)BH_*T_*T_];
__device__ __nv_bfloat16 g_plo[(size_t)BH_*T_*T_];

// ------------------------------------------------------------------
// PTX helpers
// ------------------------------------------------------------------
__device__ __forceinline__ uint32_t smem_u32(const void* p) {
    uint32_t a;
    asm("{ .reg .u64 t; cvta.to.shared.u64 t, %1; cvt.u32.u64 %0, t; }" : "=r"(a) : "l"(p));
    return a;
}
__device__ __forceinline__ void cp16(uint32_t dst, const void* src) {
    asm volatile("cp.async.cg.shared.global [%0], [%1], 16;" :: "r"(dst), "l"(src));
}
__device__ __forceinline__ void cp_commit() {
    asm volatile("cp.async.commit_group;" ::: "memory");
}
__device__ __forceinline__ void ldmx4(uint32_t* r, uint32_t addr) {
    asm volatile("ldmatrix.sync.aligned.m8n8.x4.shared.b16 {%0,%1,%2,%3}, [%4];"
                 : "=r"(r[0]), "=r"(r[1]), "=r"(r[2]), "=r"(r[3]) : "r"(addr));
}
__device__ __forceinline__ void ldmx4t(uint32_t* r, uint32_t addr) {
    asm volatile("ldmatrix.sync.aligned.m8n8.x4.trans.shared.b16 {%0,%1,%2,%3}, [%4];"
                 : "=r"(r[0]), "=r"(r[1]), "=r"(r[2]), "=r"(r[3]) : "r"(addr));
}
__device__ __forceinline__ void mma16816(float* d, const uint32_t* a, const uint32_t* b) {
    asm volatile(
        "mma.sync.aligned.m16n8k16.row.col.f32.bf16.bf16.f32 "
        "{%0,%1,%2,%3}, {%4,%5,%6,%7}, {%8,%9}, {%0,%1,%2,%3};"
        : "+f"(d[0]), "+f"(d[1]), "+f"(d[2]), "+f"(d[3])
        : "r"(a[0]), "r"(a[1]), "r"(a[2]), "r"(a[3]), "r"(b[0]), "r"(b[1]));
}
// Swizzled offset within a [rows][32 bf16] tile (64B rows)
__device__ __forceinline__ uint32_t swz(int r, int c) {
    return (uint32_t)(r * 64 + ((c ^ ((r >> 1) & 3)) << 4));
}

#define SCALE 0.08838834764831845f

// ------------------------------------------------------------------
// fp32 -> bf16 hi/lo split
// ------------------------------------------------------------------
__global__ __launch_bounds__(256)
void split_kernel(const float4* __restrict__ src, int dst_sel, int n4)
{
    int i = blockIdx.x * 256 + threadIdx.x;
    if (i >= n4) return;
    __nv_bfloat16* hi;
    __nv_bfloat16* lo;
    if (dst_sel == 0)      { hi = g_xhi; lo = g_xlo; }
    else                   { hi = g_whi + (size_t)(dst_sel - 1) * C_ * C_;
                             lo = g_wlo + (size_t)(dst_sel - 1) * C_ * C_; }
    float4 v = src[i];
    __nv_bfloat16 h0 = __float2bfloat16(v.x);
    __nv_bfloat16 h1 = __float2bfloat16(v.y);
    __nv_bfloat16 h2 = __float2bfloat16(v.z);
    __nv_bfloat16 h3 = __float2bfloat16(v.w);
    __nv_bfloat16 l0 = __float2bfloat16(v.x - __bfloat162float(h0));
    __nv_bfloat16 l1 = __float2bfloat16(v.y - __bfloat162float(h1));
    __nv_bfloat16 l2 = __float2bfloat16(v.z - __bfloat162float(h2));
    __nv_bfloat16 l3 = __float2bfloat16(v.w - __bfloat162float(h3));
    __nv_bfloat162* hp = (__nv_bfloat162*)hi;
    __nv_bfloat162* lp = (__nv_bfloat162*)lo;
    hp[2*i]   = __halves2bfloat162(h0, h1);
    hp[2*i+1] = __halves2bfloat162(h2, h3);
    lp[2*i]   = __halves2bfloat162(l0, l1);
    lp[2*i+1] = __halves2bfloat162(l2, l3);
}

// ------------------------------------------------------------------
// Main HMMA GEMM (unchanged structure from passing round)
// mode 1: x @ w{q,k,v}^T -> g_q/g_k fp32, V -> g_vhi/g_vlo bf16
// mode 0: y @ wo^T -> Out fp32
// ------------------------------------------------------------------
#define STAGES 4
#define STAGE_BYTES 32768
#define GEMM_SMEM (1024 + STAGES*STAGE_BYTES)

__global__ __launch_bounds__(256, 1)
void gemm_mma(float* __restrict__ Out, int mode)
{
    extern __shared__ char dsm[];
    const int tid  = threadIdx.x;
    const int wid  = tid >> 5;
    const int lane = tid & 31;
    const int bn = blockIdx.x * 128;
    const int bm = blockIdx.y * 128;
    const int wz = blockIdx.z;

    const __nv_bfloat16* Ahi_g = (mode == 0) ? g_yhi : g_xhi;
    const __nv_bfloat16* Alo_g = (mode == 0) ? g_ylo : g_xlo;
    const int widx = (mode == 0) ? 3 : wz;
    const __nv_bfloat16* Bhi_g = g_whi + (size_t)widx * C_ * C_;
    const __nv_bfloat16* Blo_g = g_wlo + (size_t)widx * C_ * C_;

    const uint32_t base = (smem_u32(dsm) + 1023u) & ~1023u;

    const int j0 = tid;
    const int r0l = j0 >> 2,         c0l = j0 & 3;
    const int r1l = (j0 + 256) >> 2, c1l = (j0 + 256) & 3;
    const uint32_t ph0 = swz(r0l, c0l);
    const uint32_t ph1 = swz(r1l, c1l);

    auto load_stage = [&](int kt, int s) {
        const uint32_t sb = base + (uint32_t)s * STAGE_BYTES;
        const int kb = kt * 32;
        {
            const size_t ga = (size_t)(bm + r0l) * C_ + kb + c0l * 8;
            const size_t gb = (size_t)(bn + r0l) * C_ + kb + c0l * 8;
            cp16(sb + ph0,         Ahi_g + ga);
            cp16(sb + 8192  + ph0, Alo_g + ga);
            cp16(sb + 16384 + ph0, Bhi_g + gb);
            cp16(sb + 24576 + ph0, Blo_g + gb);
        }
        {
            const size_t ga = (size_t)(bm + r1l) * C_ + kb + c1l * 8;
            const size_t gb = (size_t)(bn + r1l) * C_ + kb + c1l * 8;
            cp16(sb + ph1,         Ahi_g + ga);
            cp16(sb + 8192  + ph1, Alo_g + ga);
            cp16(sb + 16384 + ph1, Bhi_g + gb);
            cp16(sb + 24576 + ph1, Blo_g + gb);
        }
        cp_commit();
    };

    const int wm = (wid >> 1) * 32;
    const int wn = (wid & 1) * 64;

    float acc[2][8][4];
    #pragma unroll
    for (int i = 0; i < 2; i++)
        #pragma unroll
        for (int j = 0; j < 8; j++)
            #pragma unroll
            for (int q = 0; q < 4; q++) acc[i][j][q] = 0.0f;

    const int arow = wm + (lane & 15);
    const int acol_base = (lane >> 4);
    const int brow = wn + (lane & 7) + ((lane & 16) >> 1);
    const int bcol_base = ((lane >> 3) & 1);

    const int NK = C_ / 32;

    load_stage(0, 0);
    load_stage(1, 1);
    load_stage(2, 2);

    for (int c = 0; c < NK; c++) {
        __syncthreads();
        if (c + 3 < NK) load_stage(c + 3, (c + 3) & 3);
        else            cp_commit();
        asm volatile("cp.async.wait_group 3;" ::: "memory");
        __syncthreads();

        const uint32_t sA   = base + (uint32_t)(c & 3) * STAGE_BYTES;
        const uint32_t sAlo = sA + 8192;
        const uint32_t sB   = sA + 16384;
        const uint32_t sBlo = sA + 24576;

        #pragma unroll
        for (int ks = 0; ks < 2; ks++) {
            uint32_t ah[2][4], al[2][4];
            #pragma unroll
            for (int mt = 0; mt < 2; mt++) {
                const uint32_t ph = swz(arow + mt * 16, ks * 2 + acol_base);
                ldmx4(ah[mt], sA   + ph);
                ldmx4(al[mt], sAlo + ph);
            }
            uint32_t bh[8][2], bl[8][2];
            #pragma unroll
            for (int ng = 0; ng < 4; ng++) {
                const uint32_t ph = swz(brow + ng * 16, ks * 2 + bcol_base);
                uint32_t q[4];
                ldmx4(q, sB + ph);
                bh[2*ng][0] = q[0]; bh[2*ng][1] = q[1];
                bh[2*ng+1][0] = q[2]; bh[2*ng+1][1] = q[3];
                ldmx4(q, sBlo + ph);
                bl[2*ng][0] = q[0]; bl[2*ng][1] = q[1];
                bl[2*ng+1][0] = q[2]; bl[2*ng+1][1] = q[3];
            }
            #pragma unroll
            for (int mt = 0; mt < 2; mt++)
                #pragma unroll
                for (int nt = 0; nt < 8; nt++)
                    mma16816(acc[mt][nt], ah[mt], bh[nt]);
            #pragma unroll
            for (int mt = 0; mt < 2; mt++)
                #pragma unroll
                for (int nt = 0; nt < 8; nt++)
                    mma16816(acc[mt][nt], ah[mt], bl[nt]);
            #pragma unroll
            for (int mt = 0; mt < 2; mt++)
                #pragma unroll
                for (int nt = 0; nt < 8; nt++)
                    mma16816(acc[mt][nt], al[mt], bh[nt]);
        }
    }

    float* qkv = (wz == 0) ? g_q : g_k;
    #pragma unroll
    for (int mt = 0; mt < 2; mt++) {
        const int row0 = bm + wm + mt * 16 + (lane >> 2);
        #pragma unroll
        for (int nt = 0; nt < 8; nt++) {
            const int col = bn + wn + nt * 8 + (lane & 3) * 2;
            #pragma unroll
            for (int half = 0; half < 2; half++) {
                const int row = row0 + half * 8;
                float y0 = acc[mt][nt][half * 2 + 0];
                float y1 = acc[mt][nt][half * 2 + 1];
                if (mode == 0) {
                    float2 v; v.x = y0; v.y = y1;
                    *(float2*)(Out + (size_t)row * C_ + col) = v;
                } else {
                    const int b = row >> 8, t = row & 255;
                    const int h = col >> 7, d0 = col & 127;
                    const size_t ix = (((size_t)b * H_ + h) * T_ + t) * D_ + d0;
                    if (wz < 2) {
                        float2 v; v.x = y0; v.y = y1;
                        *(float2*)(qkv + ix) = v;
                    } else {
                        __nv_bfloat16 h0 = __float2bfloat16(y0);
                        __nv_bfloat16 h1 = __float2bfloat16(y1);
                        __nv_bfloat16 l0 = __float2bfloat16(y0 - __bfloat162float(h0));
                        __nv_bfloat16 l1 = __float2bfloat16(y1 - __bfloat162float(h1));
                        *(__nv_bfloat162*)(g_vhi + ix) = __halves2bfloat162(h0, h1);
                        *(__nv_bfloat162*)(g_vlo + ix) = __halves2bfloat162(l0, l1);
                    }
                }
            }
        }
    }
}

// ------------------------------------------------------------------
// RoPE tables + application (fp32 in, bf16 hi/lo out)
// ------------------------------------------------------------------
__global__ void rope_table_kernel()
{
    int idx = blockIdx.x * blockDim.x + threadIdx.x;
    if (idx >= T_ * 64) return;
    int j = idx & 63;
    int t = idx >> 6;
    double inv = exp(-(double)j * (9.210340371976184 / 64.0));
    double th = (double)t * inv;
    g_cos[idx] = (float)cos(th);
    g_sin[idx] = (float)sin(th);
}

__global__ __launch_bounds__(256)
void rope_split_kernel()
{
    int idx = blockIdx.x * 256 + threadIdx.x;   // 2*512*256*64
    int j = idx & 63;
    int t = (idx >> 6) & 255;
    int rest = idx >> 14;
    int bh = rest & 511;
    int isK = rest >> 9;
    const float* src = (isK ? g_k : g_q) + ((size_t)bh * T_ + t) * D_ + j;
    float c = g_cos[t * 64 + j];
    float s = g_sin[t * 64 + j];
    float x0 = src[0], x1 = src[64];
    float r0 = x0 * c - x1 * s;
    float r1 = x1 * c + x0 * s;
    __nv_bfloat16* dh = isK ? g_khi : g_qhi;
    __nv_bfloat16* dl = isK ? g_klo : g_qlo;
    const size_t bx = ((size_t)bh * T_ + t) * D_ + j;
    __nv_bfloat16 h0 = __float2bfloat16(r0);
    __nv_bfloat16 h1 = __float2bfloat16(r1);
    dh[bx]      = h0;
    dh[bx + 64] = h1;
    dl[bx]      = __float2bfloat16(r0 - __bfloat162float(h0));
    dl[bx + 64] = __float2bfloat16(r1 - __bfloat162float(h1));
}

// ------------------------------------------------------------------
// attn_qk: S[q][k] = Q[q][:]·K[k][:]  (raw, scaled later)
// blockIdx.x = causal tile pair (0:(q0,k0), 1:(q1,k0), 2:(q1,k1)); y = bh
// ------------------------------------------------------------------
#define QK_SMEM (1024 + 4*32768)

__global__ __launch_bounds__(256, 1)
void attn_qk()
{
    extern __shared__ char dsm[];
    const int tid  = threadIdx.x;
    const int wid  = tid >> 5;
    const int lane = tid & 31;
    const int pair = blockIdx.x;
    const int bh   = blockIdx.y;
    const int qt   = pair ? 1 : 0;
    const int kt   = (pair == 2) ? 1 : 0;

    const __nv_bfloat16* Qh = g_qhi + ((size_t)bh * T_ + qt * 128) * D_;
    const __nv_bfloat16* Ql = g_qlo + ((size_t)bh * T_ + qt * 128) * D_;
    const __nv_bfloat16* Kh = g_khi + ((size_t)bh * T_ + kt * 128) * D_;
    const __nv_bfloat16* Kl = g_klo + ((size_t)bh * T_ + kt * 128) * D_;

    const uint32_t base = (smem_u32(dsm) + 1023u) & ~1023u;

    // load all 4 tiles (chunked [4][128][32] swizzled layout each)
    #pragma unroll
    for (int it = 0; it < 8; it++) {
        int idx = tid + it * 256;            // 0..2047
        int r = idx >> 4, d16 = idx & 15;
        int c = d16 >> 2, ic = d16 & 3;
        uint32_t off = (uint32_t)c * 8192 + swz(r, ic);
        size_t g = (size_t)r * D_ + d16 * 8;
        cp16(base + off,          Qh + g);
        cp16(base + 32768 + off,  Ql + g);
        cp16(base + 65536 + off,  Kh + g);
        cp16(base + 98304 + off,  Kl + g);
    }
    cp_commit();
    asm volatile("cp.async.wait_group 0;" ::: "memory");
    __syncthreads();

    const int wm = (wid >> 1) * 32;
    const int wn = (wid & 1) * 64;
    const int arow = wm + (lane & 15);
    const int acol_base = (lane >> 4);
    const int brow = wn + (lane & 7) + ((lane & 16) >> 1);
    const int bcol_base = ((lane >> 3) & 1);

    float acc[2][8][4];
    #pragma unroll
    for (int i = 0; i < 2; i++)
        #pragma unroll
        for (int j = 0; j < 8; j++)
            #pragma unroll
            for (int q = 0; q < 4; q++) acc[i][j][q] = 0.0f;

    #pragma unroll
    for (int c = 0; c < 4; c++) {
        const uint32_t sA   = base + (uint32_t)c * 8192;
        const uint32_t sAlo = sA + 32768;
        const uint32_t sB   = sA + 65536;
        const uint32_t sBlo = sA + 98304;
        #pragma unroll
        for (int ks = 0; ks < 2; ks++) {
            uint32_t ah[2][4], al[2][4];
            #pragma unroll
            for (int mt = 0; mt < 2; mt++) {
                const uint32_t ph = swz(arow + mt * 16, ks * 2 + acol_base);
                ldmx4(ah[mt], sA   + ph);
                ldmx4(al[mt], sAlo + ph);
            }
            uint32_t bh_[8][2], bl_[8][2];
            #pragma unroll
            for (int ng = 0; ng < 4; ng++) {
                const uint32_t ph = swz(brow + ng * 16, ks * 2 + bcol_base);
                uint32_t q[4];
                ldmx4(q, sB + ph);
                bh_[2*ng][0] = q[0]; bh_[2*ng][1] = q[1];
                bh_[2*ng+1][0] = q[2]; bh_[2*ng+1][1] = q[3];
                ldmx4(q, sBlo + ph);
                bl_[2*ng][0] = q[0]; bl_[2*ng][1] = q[1];
                bl_[2*ng+1][0] = q[2]; bl_[2*ng+1][1] = q[3];
            }
            #pragma unroll
            for (int mt = 0; mt < 2; mt++)
                #pragma unroll
                for (int nt = 0; nt < 8; nt++)
                    mma16816(acc[mt][nt], ah[mt], bh_[nt]);
            #pragma unroll
            for (int mt = 0; mt < 2; mt++)
                #pragma unroll
                for (int nt = 0; nt < 8; nt++)
                    mma16816(acc[mt][nt], ah[mt], bl_[nt]);
            #pragma unroll
            for (int mt = 0; mt < 2; mt++)
                #pragma unroll
                for (int nt = 0; nt < 8; nt++)
                    mma16816(acc[mt][nt], al[mt], bh_[nt]);
        }
    }

    // store raw S
    #pragma unroll
    for (int mt = 0; mt < 2; mt++) {
        const int row0 = wm + mt * 16 + (lane >> 2);
        #pragma unroll
        for (int nt = 0; nt < 8; nt++) {
            const int col = wn + nt * 8 + (lane & 3) * 2;
            #pragma unroll
            for (int half = 0; half < 2; half++) {
                const int row = row0 + half * 8;
                float2 v;
                v.x = acc[mt][nt][half * 2 + 0];
                v.y = acc[mt][nt][half * 2 + 1];
                *(float2*)(g_s + ((size_t)bh * T_ + qt * 128 + row) * T_ + kt * 128 + col) = v;
            }
        }
    }
}

// ------------------------------------------------------------------
// softmax_p: masked softmax row-wise, emit P bf16 hi/lo (zeros padded)
// ------------------------------------------------------------------
__global__ __launch_bounds__(256)
void softmax_p()
{
    const int warp = threadIdx.x >> 5;
    const int lane = threadIdx.x & 31;
    const int row = blockIdx.x * 8 + warp;      // 0..131071
    const int bh = row >> 8;
    const int q  = row & 255;
    const size_t rb = ((size_t)bh * T_ + q) * T_;
    const int W = (q < 128) ? 128 : 256;
    const int n = W >> 5;

    float e[8];
    float m = -1e30f;
    #pragma unroll
    for (int i = 0; i < 8; i++) {
        if (i >= n) break;
        int k = lane + 32 * i;
        float v = (k <= q) ? g_s[rb + k] * SCALE : -1e30f;
        e[i] = v;
        m = fmaxf(m, v);
    }
    #pragma unroll
    for (int o = 16; o > 0; o >>= 1) m = fmaxf(m, __shfl_xor_sync(0xffffffffu, m, o));
    float sum = 0.f;
    #pragma unroll
    for (int i = 0; i < 8; i++) {
        if (i >= n) break;
        float x = __expf(e[i] - m);
        e[i] = x;
        sum += x;
    }
    #pragma unroll
    for (int o = 16; o > 0; o >>= 1) sum += __shfl_xor_sync(0xffffffffu, sum, o);
    const float inv = 1.0f / sum;
    #pragma unroll
    for (int i = 0; i < 8; i++) {
        if (i >= n) break;
        int k = lane + 32 * i;
        float p = e[i] * inv;
        __nv_bfloat16 hh = __float2bfloat16(p);
        g_phi[rb + k] = hh;
        g_plo[rb + k] = __float2bfloat16(p - __bfloat162float(hh));
    }
}

// ------------------------------------------------------------------
// attn_pv: Y = P @ V ; P as A (non-trans), V via ldmatrix.trans
// blockIdx.x = qt (0,1), y = bh. K-dim = (qt+1)*128 keys.
// ------------------------------------------------------------------
#define PV_STAGE 33792   // Phi 8192 | Plo 8192 | Vhi 8704 | Vlo 8704
#define PV_SMEM  (1024 + 2*PV_STAGE)

__global__ __launch_bounds__(256, 1)
void attn_pv()
{
    extern __shared__ char dsm[];
    const int tid  = threadIdx.x;
    const int wid  = tid >> 5;
    const int lane = tid & 31;
    const int qt = blockIdx.x;
    const int bh = blockIdx.y;

    const uint32_t base = (smem_u32(dsm) + 1023u) & ~1023u;
    const size_t prow = ((size_t)bh * T_ + qt * 128) * T_;    // P rows base
    const size_t vrow = (size_t)bh * T_ * D_;                 // V base

    auto load_stage = [&](int kc, int s) {
        const uint32_t sb = base + (uint32_t)s * PV_STAGE;
        const int kb = kc * 32;
        #pragma unroll
        for (int it = 0; it < 2; it++) {      // P: 512 chunks each
            int idx = tid + it * 256;
            int r = idx >> 2, ic = idx & 3;
            uint32_t off = swz(r, ic);
            size_t gp = prow + (size_t)r * T_ + kb + ic * 8;
            cp16(sb + off,        g_phi + gp);
            cp16(sb + 8192 + off, g_plo + gp);
        }
        #pragma unroll
        for (int it = 0; it < 2; it++) {      // V: 512 chunks each
            int idx = tid + it * 256;
            int r = idx >> 4, dc = idx & 15;
            uint32_t off = (uint32_t)r * 272 + dc * 16;
            size_t gv = vrow + (size_t)(kb + r) * D_ + dc * 8;
            cp16(sb + 16384 + off, g_vhi + gv);
            cp16(sb + 25088 + off, g_vlo + gv);
        }
        cp_commit();
    };

    const int wm = (wid >> 1) * 32;
    const int wn = (wid & 1) * 64;
    const int arow = wm + (lane & 15);
    const int acol_base = (lane >> 4);
    // trans-B lane addressing components
    const int kl_part = ((lane >> 3) & 1) * 8 + (lane & 7);
    const int nblk = lane >> 4;

    float acc[2][8][4];
    #pragma unroll
    for (int i = 0; i < 2; i++)
        #pragma unroll
        for (int j = 0; j < 8; j++)
            #pragma unroll
            for (int q = 0; q < 4; q++) acc[i][j][q] = 0.0f;

    const int nc = (qt + 1) * 4;
    load_stage(0, 0);
    load_stage(1, 1);

    for (int kc = 0; kc < nc; kc++) {
        if (kc + 1 < nc) asm volatile("cp.async.wait_group 1;" ::: "memory");
        else             asm volatile("cp.async.wait_group 0;" ::: "memory");
        __syncthreads();

        const uint32_t sb   = base + (uint32_t)(kc & 1) * PV_STAGE;
        const uint32_t sPlo = sb + 8192;
        const uint32_t sV   = sb + 16384;

        #pragma unroll
        for (int ks = 0; ks < 2; ks++) {
            uint32_t ah[2][4], al[2][4];
            #pragma unroll
            for (int mt = 0; mt < 2; mt++) {
                const uint32_t ph = swz(arow + mt * 16, ks * 2 + acol_base);
                ldmx4(ah[mt], sb   + ph);
                ldmx4(al[mt], sPlo + ph);
            }
            uint32_t bh_[8][2], bl_[8][2];
            #pragma unroll
            for (int dp = 0; dp < 4; dp++) {
                const uint32_t addr = sV + (uint32_t)(ks * 16 + kl_part) * 272
                                    + (uint32_t)((wn >> 3) + dp * 2 + nblk) * 16;
                uint32_t q[4];
                ldmx4t(q, addr);
                bh_[2*dp][0] = q[0]; bh_[2*dp][1] = q[1];
                bh_[2*dp+1][0] = q[2]; bh_[2*dp+1][1] = q[3];
                ldmx4t(q, addr + 8704);
                bl_[2*dp][0] = q[0]; bl_[2*dp][1] = q[1];
                bl_[2*dp+1][0] = q[2]; bl_[2*dp+1][1] = q[3];
            }
            #pragma unroll
            for (int mt = 0; mt < 2; mt++)
                #pragma unroll
                for (int nt = 0; nt < 8; nt++)
                    mma16816(acc[mt][nt], ah[mt], bh_[nt]);
            #pragma unroll
            for (int mt = 0; mt < 2; mt++)
                #pragma unroll
                for (int nt = 0; nt < 8; nt++)
                    mma16816(acc[mt][nt], ah[mt], bl_[nt]);
            #pragma unroll
            for (int mt = 0; mt < 2; mt++)
                #pragma unroll
                for (int nt = 0; nt < 8; nt++)
                    mma16816(acc[mt][nt], al[mt], bh_[nt]);
        }
        __syncthreads();
        if (kc + 2 < nc) load_stage(kc + 2, kc & 1);
    }

    // epilogue: write y bf16 hi/lo into [B,T,C]
    const int b = bh >> 4, h = bh & 15;
    #pragma unroll
    for (int mt = 0; mt < 2; mt++) {
        const int row0 = qt * 128 + wm + mt * 16 + (lane >> 2);
        #pragma unroll
        for (int nt = 0; nt < 8; nt++) {
            const int d = wn + nt * 8 + (lane & 3) * 2;
            #pragma unroll
            for (int half = 0; half < 2; half++) {
                const int t = row0 + half * 8;
                float y0 = acc[mt][nt][half * 2 + 0];
                float y1 = acc[mt][nt][half * 2 + 1];
                __nv_bfloat16 h0 = __float2bfloat16(y0);
                __nv_bfloat16 h1 = __float2bfloat16(y1);
                __nv_bfloat16 l0 = __float2bfloat16(y0 - __bfloat162float(h0));
                __nv_bfloat16 l1 = __float2bfloat16(y1 - __bfloat162float(h1));
                const size_t ix = ((size_t)b * T_ + t) * C_ + h * D_ + d;
                *(__nv_bfloat162*)(g_yhi + ix) = __halves2bfloat162(h0, h1);
                *(__nv_bfloat162*)(g_ylo + ix) = __halves2bfloat162(l0, l1);
            }
        }
    }
}

// ------------------------------------------------------------------
extern "C" void kernel_launch(void* const* d_in, const int* in_sizes, int n_in,
                              void* d_out, int out_size)
{
    const float* x  = (const float*)d_in[0];
    const float* wq = (const float*)d_in[1];
    const float* wk = (const float*)d_in[2];
    const float* wv = (const float*)d_in[3];
    const float* wo = (const float*)d_in[4];
    float* out = (float*)d_out;

    const int nx4 = M_TOT * C_ / 4;
    const int nw4 = C_ * C_ / 4;
    split_kernel<<<(nx4 + 255)/256, 256>>>((const float4*)x,  0, nx4);
    split_kernel<<<(nw4 + 255)/256, 256>>>((const float4*)wq, 1, nw4);
    split_kernel<<<(nw4 + 255)/256, 256>>>((const float4*)wk, 2, nw4);
    split_kernel<<<(nw4 + 255)/256, 256>>>((const float4*)wv, 3, nw4);
    split_kernel<<<(nw4 + 255)/256, 256>>>((const float4*)wo, 4, nw4);

    cudaFuncSetAttribute(gemm_mma, cudaFuncAttributeMaxDynamicSharedMemorySize, GEMM_SMEM);
    cudaFuncSetAttribute(attn_qk,  cudaFuncAttributeMaxDynamicSharedMemorySize, QK_SMEM);
    cudaFuncSetAttribute(attn_pv,  cudaFuncAttributeMaxDynamicSharedMemorySize, PV_SMEM);

    // QKV projections
    gemm_mma<<<dim3(C_/128, M_TOT/128, 3), 256, GEMM_SMEM>>>(nullptr, 1);

    // RoPE -> bf16 hi/lo Q,K
    rope_table_kernel<<<(T_*64 + 255)/256, 256>>>();
    rope_split_kernel<<<(2 * BH_ * T_ * 64) / 256, 256>>>();

    // Attention: S = QK^T (causal tiles), softmax, Y = PV
    attn_qk<<<dim3(3, BH_), 256, QK_SMEM>>>();
    softmax_p<<<(BH_ * T_) / 8, 256>>>();
    attn_pv<<<dim3(2, BH_), 256, PV_SMEM>>>();

    // Output projection
    gemm_mma<<<dim3(C_/128, M_TOT/128, 1), 256, GEMM_SMEM>>>(out, 0);
}

// round 5
// speedup vs baseline: 5.9205x; 2.2307x over previous
#include <cuda_runtime.h>
#include <cuda_bf16.h>
#include <cuda_fp16.h>
#include <cstdint>

#define B_  32
#define T_  256
#define C_  2048
#define H_  16
#define D_  128
#define M_TOT (B_*T_)     // 8192
#define BH_  (B_*H_)      // 512

// ------------------------------------------------------------------
// Device globals
// ------------------------------------------------------------------
__device__ float g_q[(size_t)BH_*T_*D_];        // fp32 Q pre-rope
__device__ float g_k[(size_t)BH_*T_*D_];        // fp32 K pre-rope
__device__ float g_cos[T_*64];
__device__ float g_sin[T_*64];
__device__ __half g_x16[(size_t)M_TOT*C_];
__device__ __half g_w16[(size_t)4*C_*C_];
__device__ __half g_y16[(size_t)M_TOT*C_];
__device__ __nv_bfloat16 g_qhi[(size_t)BH_*T_*D_];
__device__ __nv_bfloat16 g_qlo[(size_t)BH_*T_*D_];
__device__ __nv_bfloat16 g_khi[(size_t)BH_*T_*D_];
__device__ __nv_bfloat16 g_klo[(size_t)BH_*T_*D_];
__device__ __nv_bfloat16 g_vhi[(size_t)BH_*T_*D_];
__device__ __nv_bfloat16 g_vlo[(size_t)BH_*T_*D_];
__device__ float g_s[(size_t)BH_*T_*T_];
__device__ __nv_bfloat16 g_phi[(size_t)BH_*T_*T_];
__device__ __nv_bfloat16 g_plo[(size_t)BH_*T_*T_];

// ------------------------------------------------------------------
// PTX helpers
// ------------------------------------------------------------------
__device__ __forceinline__ uint32_t smem_u32(const void* p) {
    uint32_t a;
    asm("{ .reg .u64 t; cvta.to.shared.u64 t, %1; cvt.u32.u64 %0, t; }" : "=r"(a) : "l"(p));
    return a;
}
__device__ __forceinline__ void cp16(uint32_t dst, const void* src) {
    asm volatile("cp.async.cg.shared.global [%0], [%1], 16;" :: "r"(dst), "l"(src));
}
__device__ __forceinline__ void cp_commit() {
    asm volatile("cp.async.commit_group;" ::: "memory");
}
__device__ __forceinline__ void ldmx4(uint32_t* r, uint32_t addr) {
    asm volatile("ldmatrix.sync.aligned.m8n8.x4.shared.b16 {%0,%1,%2,%3}, [%4];"
                 : "=r"(r[0]), "=r"(r[1]), "=r"(r[2]), "=r"(r[3]) : "r"(addr));
}
__device__ __forceinline__ void ldmx4t(uint32_t* r, uint32_t addr) {
    asm volatile("ldmatrix.sync.aligned.m8n8.x4.trans.shared.b16 {%0,%1,%2,%3}, [%4];"
                 : "=r"(r[0]), "=r"(r[1]), "=r"(r[2]), "=r"(r[3]) : "r"(addr));
}
__device__ __forceinline__ void mma16816(float* d, const uint32_t* a, const uint32_t* b) {
    asm volatile(
        "mma.sync.aligned.m16n8k16.row.col.f32.bf16.bf16.f32 "
        "{%0,%1,%2,%3}, {%4,%5,%6,%7}, {%8,%9}, {%0,%1,%2,%3};"
        : "+f"(d[0]), "+f"(d[1]), "+f"(d[2]), "+f"(d[3])
        : "r"(a[0]), "r"(a[1]), "r"(a[2]), "r"(a[3]), "r"(b[0]), "r"(b[1]));
}
__device__ __forceinline__ void mma16816h(float* d, const uint32_t* a, const uint32_t* b) {
    asm volatile(
        "mma.sync.aligned.m16n8k16.row.col.f32.f16.f16.f32 "
        "{%0,%1,%2,%3}, {%4,%5,%6,%7}, {%8,%9}, {%0,%1,%2,%3};"
        : "+f"(d[0]), "+f"(d[1]), "+f"(d[2]), "+f"(d[3])
        : "r"(a[0]), "r"(a[1]), "r"(a[2]), "r"(a[3]), "r"(b[0]), "r"(b[1]));
}
// Swizzle for [rows][32 bf16] tiles (64B rows)
__device__ __forceinline__ uint32_t swz(int r, int c) {
    return (uint32_t)(r * 64 + ((c ^ ((r >> 1) & 3)) << 4));
}
// Swizzle for [rows][64 fp16] tiles (128B rows, full SW128 atom)
__device__ __forceinline__ uint32_t swz128(int r, int c) {
    return (uint32_t)(r * 128 + ((c ^ (r & 7)) << 4));
}

#define SCALE 0.08838834764831845f

// ------------------------------------------------------------------
// fp32 -> fp16 conversion
// ------------------------------------------------------------------
__global__ __launch_bounds__(256)
void split16_kernel(const float4* __restrict__ src, int dst_sel, int n4)
{
    int i = blockIdx.x * 256 + threadIdx.x;
    if (i >= n4) return;
    __half* dst = (dst_sel == 0) ? g_x16 : (g_w16 + (size_t)(dst_sel - 1) * C_ * C_);
    float4 v = src[i];
    __half2* dp = (__half2*)dst;
    dp[2*i]   = __floats2half2_rn(v.x, v.y);
    dp[2*i+1] = __floats2half2_rn(v.z, v.w);
}

// ------------------------------------------------------------------
// fp16 single-term HMMA GEMM. CTA tile 128x128, BK=64, 4 stages.
// mode 1: g_x16 @ g_w16[z]^T -> Q/K fp32, V bf16 hi/lo ([B,H,T,D])
// mode 0: g_y16 @ g_w16[3]^T -> Out fp32 [M, C]
// ------------------------------------------------------------------
#define G16_STAGE 32768             // A 16KB | B 16KB
#define G16_SMEM (1024 + 4*G16_STAGE)

__global__ __launch_bounds__(256, 1)
void gemm16(float* __restrict__ Out, int mode)
{
    extern __shared__ char dsm[];
    const int tid  = threadIdx.x;
    const int wid  = tid >> 5;
    const int lane = tid & 31;
    const int bn = blockIdx.x * 128;
    const int bm = blockIdx.y * 128;
    const int wz = blockIdx.z;

    const __half* A_g = (mode == 0) ? g_y16 : g_x16;
    const int widx = (mode == 0) ? 3 : wz;
    const __half* B_g = g_w16 + (size_t)widx * C_ * C_;

    const uint32_t base = (smem_u32(dsm) + 1023u) & ~1023u;

    auto load_stage = [&](int kt, int s) {
        const uint32_t sb = base + (uint32_t)s * G16_STAGE;
        const int kb = kt * 64;
        #pragma unroll
        for (int it = 0; it < 4; it++) {
            int idx = tid + it * 256;          // 0..1023
            int r = idx >> 3, c = idx & 7;
            uint32_t off = swz128(r, c);
            cp16(sb + off,         A_g + (size_t)(bm + r) * C_ + kb + c * 8);
            cp16(sb + 16384 + off, B_g + (size_t)(bn + r) * C_ + kb + c * 8);
        }
        cp_commit();
    };

    const int wm = (wid >> 1) * 32;
    const int wn = (wid & 1) * 64;
    const int arow = wm + (lane & 15);
    const int acol_base = (lane >> 4);
    const int brow = wn + (lane & 7) + ((lane & 16) >> 1);
    const int bcol_base = ((lane >> 3) & 1);

    float acc[2][8][4];
    #pragma unroll
    for (int i = 0; i < 2; i++)
        #pragma unroll
        for (int j = 0; j < 8; j++)
            #pragma unroll
            for (int q = 0; q < 4; q++) acc[i][j][q] = 0.0f;

    const int NK = C_ / 64;    // 32

    load_stage(0, 0);
    load_stage(1, 1);
    load_stage(2, 2);

    for (int c = 0; c < NK; c++) {
        __syncthreads();
        if (c + 3 < NK) load_stage(c + 3, (c + 3) & 3);
        else            cp_commit();
        asm volatile("cp.async.wait_group 3;" ::: "memory");
        __syncthreads();

        const uint32_t sA = base + (uint32_t)(c & 3) * G16_STAGE;
        const uint32_t sB = sA + 16384;

        #pragma unroll
        for (int ks = 0; ks < 4; ks++) {
            uint32_t ah[2][4];
            #pragma unroll
            for (int mt = 0; mt < 2; mt++)
                ldmx4(ah[mt], sA + swz128(arow + mt * 16, ks * 2 + acol_base));
            uint32_t bh[8][2];
            #pragma unroll
            for (int ng = 0; ng < 4; ng++) {
                uint32_t q[4];
                ldmx4(q, sB + swz128(brow + ng * 16, ks * 2 + bcol_base));
                bh[2*ng][0] = q[0]; bh[2*ng][1] = q[1];
                bh[2*ng+1][0] = q[2]; bh[2*ng+1][1] = q[3];
            }
            #pragma unroll
            for (int mt = 0; mt < 2; mt++)
                #pragma unroll
                for (int nt = 0; nt < 8; nt++)
                    mma16816h(acc[mt][nt], ah[mt], bh[nt]);
        }
    }

    float* qkv = (wz == 0) ? g_q : g_k;
    #pragma unroll
    for (int mt = 0; mt < 2; mt++) {
        const int row0 = bm + wm + mt * 16 + (lane >> 2);
        #pragma unroll
        for (int nt = 0; nt < 8; nt++) {
            const int col = bn + wn + nt * 8 + (lane & 3) * 2;
            #pragma unroll
            for (int half = 0; half < 2; half++) {
                const int row = row0 + half * 8;
                float y0 = acc[mt][nt][half * 2 + 0];
                float y1 = acc[mt][nt][half * 2 + 1];
                if (mode == 0) {
                    float2 v; v.x = y0; v.y = y1;
                    *(float2*)(Out + (size_t)row * C_ + col) = v;
                } else {
                    const int b = row >> 8, t = row & 255;
                    const int h = col >> 7, d0 = col & 127;
                    const size_t ix = (((size_t)b * H_ + h) * T_ + t) * D_ + d0;
                    if (wz < 2) {
                        float2 v; v.x = y0; v.y = y1;
                        *(float2*)(qkv + ix) = v;
                    } else {
                        __nv_bfloat16 h0 = __float2bfloat16(y0);
                        __nv_bfloat16 h1 = __float2bfloat16(y1);
                        __nv_bfloat16 l0 = __float2bfloat16(y0 - __bfloat162float(h0));
                        __nv_bfloat16 l1 = __float2bfloat16(y1 - __bfloat162float(h1));
                        *(__nv_bfloat162*)(g_vhi + ix) = __halves2bfloat162(h0, h1);
                        *(__nv_bfloat162*)(g_vlo + ix) = __halves2bfloat162(l0, l1);
                    }
                }
            }
        }
    }
}

// ------------------------------------------------------------------
// RoPE tables + application (fp32 in, bf16 hi/lo out)
// ------------------------------------------------------------------
__global__ void rope_table_kernel()
{
    int idx = blockIdx.x * blockDim.x + threadIdx.x;
    if (idx >= T_ * 64) return;
    int j = idx & 63;
    int t = idx >> 6;
    double inv = exp(-(double)j * (9.210340371976184 / 64.0));
    double th = (double)t * inv;
    g_cos[idx] = (float)cos(th);
    g_sin[idx] = (float)sin(th);
}

__global__ __launch_bounds__(256)
void rope_split_kernel()
{
    int idx = blockIdx.x * 256 + threadIdx.x;
    int j = idx & 63;
    int t = (idx >> 6) & 255;
    int rest = idx >> 14;
    int bh = rest & 511;
    int isK = rest >> 9;
    const float* src = (isK ? g_k : g_q) + ((size_t)bh * T_ + t) * D_ + j;
    float c = g_cos[t * 64 + j];
    float s = g_sin[t * 64 + j];
    float x0 = src[0], x1 = src[64];
    float r0 = x0 * c - x1 * s;
    float r1 = x1 * c + x0 * s;
    __nv_bfloat16* dh = isK ? g_khi : g_qhi;
    __nv_bfloat16* dl = isK ? g_klo : g_qlo;
    const size_t bx = ((size_t)bh * T_ + t) * D_ + j;
    __nv_bfloat16 h0 = __float2bfloat16(r0);
    __nv_bfloat16 h1 = __float2bfloat16(r1);
    dh[bx]      = h0;
    dh[bx + 64] = h1;
    dl[bx]      = __float2bfloat16(r0 - __bfloat162float(h0));
    dl[bx + 64] = __float2bfloat16(r1 - __bfloat162float(h1));
}

// ------------------------------------------------------------------
// attn_qk: S = Q·K^T (bf16 3-term split, causal tiles)
// ------------------------------------------------------------------
#define QK_SMEM (1024 + 4*32768)

__global__ __launch_bounds__(256, 1)
void attn_qk()
{
    extern __shared__ char dsm[];
    const int tid  = threadIdx.x;
    const int wid  = tid >> 5;
    const int lane = tid & 31;
    const int pair = blockIdx.x;
    const int bh   = blockIdx.y;
    const int qt   = pair ? 1 : 0;
    const int kt   = (pair == 2) ? 1 : 0;

    const __nv_bfloat16* Qh = g_qhi + ((size_t)bh * T_ + qt * 128) * D_;
    const __nv_bfloat16* Ql = g_qlo + ((size_t)bh * T_ + qt * 128) * D_;
    const __nv_bfloat16* Kh = g_khi + ((size_t)bh * T_ + kt * 128) * D_;
    const __nv_bfloat16* Kl = g_klo + ((size_t)bh * T_ + kt * 128) * D_;

    const uint32_t base = (smem_u32(dsm) + 1023u) & ~1023u;

    #pragma unroll
    for (int it = 0; it < 8; it++) {
        int idx = tid + it * 256;
        int r = idx >> 4, d16 = idx & 15;
        int c = d16 >> 2, ic = d16 & 3;
        uint32_t off = (uint32_t)c * 8192 + swz(r, ic);
        size_t g = (size_t)r * D_ + d16 * 8;
        cp16(base + off,          Qh + g);
        cp16(base + 32768 + off,  Ql + g);
        cp16(base + 65536 + off,  Kh + g);
        cp16(base + 98304 + off,  Kl + g);
    }
    cp_commit();
    asm volatile("cp.async.wait_group 0;" ::: "memory");
    __syncthreads();

    const int wm = (wid >> 1) * 32;
    const int wn = (wid & 1) * 64;
    const int arow = wm + (lane & 15);
    const int acol_base = (lane >> 4);
    const int brow = wn + (lane & 7) + ((lane & 16) >> 1);
    const int bcol_base = ((lane >> 3) & 1);

    float acc[2][8][4];
    #pragma unroll
    for (int i = 0; i < 2; i++)
        #pragma unroll
        for (int j = 0; j < 8; j++)
            #pragma unroll
            for (int q = 0; q < 4; q++) acc[i][j][q] = 0.0f;

    #pragma unroll
    for (int c = 0; c < 4; c++) {
        const uint32_t sA   = base + (uint32_t)c * 8192;
        const uint32_t sAlo = sA + 32768;
        const uint32_t sB   = sA + 65536;
        const uint32_t sBlo = sA + 98304;
        #pragma unroll
        for (int ks = 0; ks < 2; ks++) {
            uint32_t ah[2][4], al[2][4];
            #pragma unroll
            for (int mt = 0; mt < 2; mt++) {
                const uint32_t ph = swz(arow + mt * 16, ks * 2 + acol_base);
                ldmx4(ah[mt], sA   + ph);
                ldmx4(al[mt], sAlo + ph);
            }
            uint32_t bh_[8][2], bl_[8][2];
            #pragma unroll
            for (int ng = 0; ng < 4; ng++) {
                const uint32_t ph = swz(brow + ng * 16, ks * 2 + bcol_base);
                uint32_t q[4];
                ldmx4(q, sB + ph);
                bh_[2*ng][0] = q[0]; bh_[2*ng][1] = q[1];
                bh_[2*ng+1][0] = q[2]; bh_[2*ng+1][1] = q[3];
                ldmx4(q, sBlo + ph);
                bl_[2*ng][0] = q[0]; bl_[2*ng][1] = q[1];
                bl_[2*ng+1][0] = q[2]; bl_[2*ng+1][1] = q[3];
            }
            #pragma unroll
            for (int mt = 0; mt < 2; mt++)
                #pragma unroll
                for (int nt = 0; nt < 8; nt++)
                    mma16816(acc[mt][nt], ah[mt], bh_[nt]);
            #pragma unroll
            for (int mt = 0; mt < 2; mt++)
                #pragma unroll
                for (int nt = 0; nt < 8; nt++)
                    mma16816(acc[mt][nt], ah[mt], bl_[nt]);
            #pragma unroll
            for (int mt = 0; mt < 2; mt++)
                #pragma unroll
                for (int nt = 0; nt < 8; nt++)
                    mma16816(acc[mt][nt], al[mt], bh_[nt]);
        }
    }

    #pragma unroll
    for (int mt = 0; mt < 2; mt++) {
        const int row0 = wm + mt * 16 + (lane >> 2);
        #pragma unroll
        for (int nt = 0; nt < 8; nt++) {
            const int col = wn + nt * 8 + (lane & 3) * 2;
            #pragma unroll
            for (int half = 0; half < 2; half++) {
                const int row = row0 + half * 8;
                float2 v;
                v.x = acc[mt][nt][half * 2 + 0];
                v.y = acc[mt][nt][half * 2 + 1];
                *(float2*)(g_s + ((size_t)bh * T_ + qt * 128 + row) * T_ + kt * 128 + col) = v;
            }
        }
    }
}

// ------------------------------------------------------------------
// softmax_p: masked row softmax -> P bf16 hi/lo
// ------------------------------------------------------------------
__global__ __launch_bounds__(256)
void softmax_p()
{
    const int warp = threadIdx.x >> 5;
    const int lane = threadIdx.x & 31;
    const int row = blockIdx.x * 8 + warp;
    const int bh = row >> 8;
    const int q  = row & 255;
    const size_t rb = ((size_t)bh * T_ + q) * T_;
    const int W = (q < 128) ? 128 : 256;
    const int n = W >> 5;

    float e[8];
    float m = -1e30f;
    #pragma unroll
    for (int i = 0; i < 8; i++) {
        if (i >= n) break;
        int k = lane + 32 * i;
        float v = (k <= q) ? g_s[rb + k] * SCALE : -1e30f;
        e[i] = v;
        m = fmaxf(m, v);
    }
    #pragma unroll
    for (int o = 16; o > 0; o >>= 1) m = fmaxf(m, __shfl_xor_sync(0xffffffffu, m, o));
    float sum = 0.f;
    #pragma unroll
    for (int i = 0; i < 8; i++) {
        if (i >= n) break;
        float x = __expf(e[i] - m);
        e[i] = x;
        sum += x;
    }
    #pragma unroll
    for (int o = 16; o > 0; o >>= 1) sum += __shfl_xor_sync(0xffffffffu, sum, o);
    const float inv = 1.0f / sum;
    #pragma unroll
    for (int i = 0; i < 8; i++) {
        if (i >= n) break;
        int k = lane + 32 * i;
        float p = e[i] * inv;
        __nv_bfloat16 hh = __float2bfloat16(p);
        g_phi[rb + k] = hh;
        g_plo[rb + k] = __float2bfloat16(p - __bfloat162float(hh));
    }
}

// ------------------------------------------------------------------
// attn_pv: Y = P @ V (bf16 3-term); epilogue -> g_y16 fp16 [B,T,C]
// ------------------------------------------------------------------
#define PV_STAGE 33792
#define PV_SMEM  (1024 + 2*PV_STAGE)

__global__ __launch_bounds__(256, 1)
void attn_pv()
{
    extern __shared__ char dsm[];
    const int tid  = threadIdx.x;
    const int wid  = tid >> 5;
    const int lane = tid & 31;
    const int qt = blockIdx.x;
    const int bh = blockIdx.y;

    const uint32_t base = (smem_u32(dsm) + 1023u) & ~1023u;
    const size_t prow = ((size_t)bh * T_ + qt * 128) * T_;
    const size_t vrow = (size_t)bh * T_ * D_;

    auto load_stage = [&](int kc, int s) {
        const uint32_t sb = base + (uint32_t)s * PV_STAGE;
        const int kb = kc * 32;
        #pragma unroll
        for (int it = 0; it < 2; it++) {
            int idx = tid + it * 256;
            int r = idx >> 2, ic = idx & 3;
            uint32_t off = swz(r, ic);
            size_t gp = prow + (size_t)r * T_ + kb + ic * 8;
            cp16(sb + off,        g_phi + gp);
            cp16(sb + 8192 + off, g_plo + gp);
        }
        #pragma unroll
        for (int it = 0; it < 2; it++) {
            int idx = tid + it * 256;
            int r = idx >> 4, dc = idx & 15;
            uint32_t off = (uint32_t)r * 272 + dc * 16;
            size_t gv = vrow + (size_t)(kb + r) * D_ + dc * 8;
            cp16(sb + 16384 + off, g_vhi + gv);
            cp16(sb + 25088 + off, g_vlo + gv);
        }
        cp_commit();
    };

    const int wm = (wid >> 1) * 32;
    const int wn = (wid & 1) * 64;
    const int arow = wm + (lane & 15);
    const int acol_base = (lane >> 4);
    const int kl_part = ((lane >> 3) & 1) * 8 + (lane & 7);
    const int nblk = lane >> 4;

    float acc[2][8][4];
    #pragma unroll
    for (int i = 0; i < 2; i++)
        #pragma unroll
        for (int j = 0; j < 8; j++)
            #pragma unroll
            for (int q = 0; q < 4; q++) acc[i][j][q] = 0.0f;

    const int nc = (qt + 1) * 4;
    load_stage(0, 0);
    load_stage(1, 1);

    for (int kc = 0; kc < nc; kc++) {
        if (kc + 1 < nc) asm volatile("cp.async.wait_group 1;" ::: "memory");
        else             asm volatile("cp.async.wait_group 0;" ::: "memory");
        __syncthreads();

        const uint32_t sb   = base + (uint32_t)(kc & 1) * PV_STAGE;
        const uint32_t sPlo = sb + 8192;
        const uint32_t sV   = sb + 16384;

        #pragma unroll
        for (int ks = 0; ks < 2; ks++) {
            uint32_t ah[2][4], al[2][4];
            #pragma unroll
            for (int mt = 0; mt < 2; mt++) {
                const uint32_t ph = swz(arow + mt * 16, ks * 2 + acol_base);
                ldmx4(ah[mt], sb   + ph);
                ldmx4(al[mt], sPlo + ph);
            }
            uint32_t bh_[8][2], bl_[8][2];
            #pragma unroll
            for (int dp = 0; dp < 4; dp++) {
                const uint32_t addr = sV + (uint32_t)(ks * 16 + kl_part) * 272
                                    + (uint32_t)((wn >> 3) + dp * 2 + nblk) * 16;
                uint32_t q[4];
                ldmx4t(q, addr);
                bh_[2*dp][0] = q[0]; bh_[2*dp][1] = q[1];
                bh_[2*dp+1][0] = q[2]; bh_[2*dp+1][1] = q[3];
                ldmx4t(q, addr + 8704);
                bl_[2*dp][0] = q[0]; bl_[2*dp][1] = q[1];
                bl_[2*dp+1][0] = q[2]; bl_[2*dp+1][1] = q[3];
            }
            #pragma unroll
            for (int mt = 0; mt < 2; mt++)
                #pragma unroll
                for (int nt = 0; nt < 8; nt++)
                    mma16816(acc[mt][nt], ah[mt], bh_[nt]);
            #pragma unroll
            for (int mt = 0; mt < 2; mt++)
                #pragma unroll
                for (int nt = 0; nt < 8; nt++)
                    mma16816(acc[mt][nt], ah[mt], bl_[nt]);
            #pragma unroll
            for (int mt = 0; mt < 2; mt++)
                #pragma unroll
                for (int nt = 0; nt < 8; nt++)
                    mma16816(acc[mt][nt], al[mt], bh_[nt]);
        }
        __syncthreads();
        if (kc + 2 < nc) load_stage(kc + 2, kc & 1);
    }

    // epilogue: write y fp16 into [B,T,C]
    const int b = bh >> 4, h = bh & 15;
    #pragma unroll
    for (int mt = 0; mt < 2; mt++) {
        const int row0 = qt * 128 + wm + mt * 16 + (lane >> 2);
        #pragma unroll
        for (int nt = 0; nt < 8; nt++) {
            const int d = wn + nt * 8 + (lane & 3) * 2;
            #pragma unroll
            for (int half = 0; half < 2; half++) {
                const int t = row0 + half * 8;
                const size_t ix = ((size_t)b * T_ + t) * C_ + h * D_ + d;
                *(__half2*)(g_y16 + ix) =
                    __floats2half2_rn(acc[mt][nt][half * 2 + 0], acc[mt][nt][half * 2 + 1]);
            }
        }
    }
}

// ------------------------------------------------------------------
extern "C" void kernel_launch(void* const* d_in, const int* in_sizes, int n_in,
                              void* d_out, int out_size)
{
    const float* x  = (const float*)d_in[0];
    const float* wq = (const float*)d_in[1];
    const float* wk = (const float*)d_in[2];
    const float* wv = (const float*)d_in[3];
    const float* wo = (const float*)d_in[4];
    float* out = (float*)d_out;

    const int nx4 = M_TOT * C_ / 4;
    const int nw4 = C_ * C_ / 4;
    split16_kernel<<<(nx4 + 255)/256, 256>>>((const float4*)x,  0, nx4);
    split16_kernel<<<(nw4 + 255)/256, 256>>>((const float4*)wq, 1, nw4);
    split16_kernel<<<(nw4 + 255)/256, 256>>>((const float4*)wk, 2, nw4);
    split16_kernel<<<(nw4 + 255)/256, 256>>>((const float4*)wv, 3, nw4);
    split16_kernel<<<(nw4 + 255)/256, 256>>>((const float4*)wo, 4, nw4);

    cudaFuncSetAttribute(gemm16,  cudaFuncAttributeMaxDynamicSharedMemorySize, G16_SMEM);
    cudaFuncSetAttribute(attn_qk, cudaFuncAttributeMaxDynamicSharedMemorySize, QK_SMEM);
    cudaFuncSetAttribute(attn_pv, cudaFuncAttributeMaxDynamicSharedMemorySize, PV_SMEM);

    // QKV projections (fp16 single-term HMMA)
    gemm16<<<dim3(C_/128, M_TOT/128, 3), 256, G16_SMEM>>>(nullptr, 1);

    // RoPE -> bf16 hi/lo Q,K
    rope_table_kernel<<<(T_*64 + 255)/256, 256>>>();
    rope_split_kernel<<<(2 * BH_ * T_ * 64) / 256, 256>>>();

    // Attention
    attn_qk<<<dim3(3, BH_), 256, QK_SMEM>>>();
    softmax_p<<<(BH_ * T_) / 8, 256>>>();
    attn_pv<<<dim3(2, BH_), 256, PV_SMEM>>>();

    // Output projection (fp16 single-term HMMA)
    gemm16<<<dim3(C_/128, M_TOT/128, 1), 256, G16_SMEM>>>(out, 0);
}

// round 6
// speedup vs baseline: 7.5788x; 1.2801x over previous
#include <cuda_runtime.h>
#include <cuda_bf16.h>
#include <cuda_fp16.h>
#include <cstdint>

#define B_  32
#define T_  256
#define C_  2048
#define H_  16
#define D_  128
#define M_TOT (B_*T_)     // 8192
#define BH_  (B_*H_)      // 512

// ------------------------------------------------------------------
// Device globals
// ------------------------------------------------------------------
__device__ float g_q[(size_t)BH_*T_*D_];        // fp32 Q pre-rope
__device__ float g_k[(size_t)BH_*T_*D_];        // fp32 K pre-rope
__device__ float g_cos[T_*64];
__device__ float g_sin[T_*64];
__device__ __half g_x16[(size_t)M_TOT*C_];
__device__ __half g_w16[(size_t)4*C_*C_];
__device__ __half g_y16[(size_t)M_TOT*C_];
__device__ __half g_q16[(size_t)BH_*T_*D_];
__device__ __half g_k16[(size_t)BH_*T_*D_];
__device__ __half g_v16[(size_t)BH_*T_*D_];
__device__ __half g_s16[(size_t)BH_*T_*T_];
__device__ __half g_p16[(size_t)BH_*T_*T_];

// ------------------------------------------------------------------
// PTX helpers
// ------------------------------------------------------------------
__device__ __forceinline__ uint32_t smem_u32(const void* p) {
    uint32_t a;
    asm("{ .reg .u64 t; cvta.to.shared.u64 t, %1; cvt.u32.u64 %0, t; }" : "=r"(a) : "l"(p));
    return a;
}
__device__ __forceinline__ void cp16(uint32_t dst, const void* src) {
    asm volatile("cp.async.cg.shared.global [%0], [%1], 16;" :: "r"(dst), "l"(src));
}
__device__ __forceinline__ void cp_commit() {
    asm volatile("cp.async.commit_group;" ::: "memory");
}
__device__ __forceinline__ void ldmx4(uint32_t* r, uint32_t addr) {
    asm volatile("ldmatrix.sync.aligned.m8n8.x4.shared.b16 {%0,%1,%2,%3}, [%4];"
                 : "=r"(r[0]), "=r"(r[1]), "=r"(r[2]), "=r"(r[3]) : "r"(addr));
}
__device__ __forceinline__ void ldmx4t(uint32_t* r, uint32_t addr) {
    asm volatile("ldmatrix.sync.aligned.m8n8.x4.trans.shared.b16 {%0,%1,%2,%3}, [%4];"
                 : "=r"(r[0]), "=r"(r[1]), "=r"(r[2]), "=r"(r[3]) : "r"(addr));
}
__device__ __forceinline__ void mma16816h(float* d, const uint32_t* a, const uint32_t* b) {
    asm volatile(
        "mma.sync.aligned.m16n8k16.row.col.f32.f16.f16.f32 "
        "{%0,%1,%2,%3}, {%4,%5,%6,%7}, {%8,%9}, {%0,%1,%2,%3};"
        : "+f"(d[0]), "+f"(d[1]), "+f"(d[2]), "+f"(d[3])
        : "r"(a[0]), "r"(a[1]), "r"(a[2]), "r"(a[3]), "r"(b[0]), "r"(b[1]));
}
// Swizzle for [rows][32 x 16-bit] tiles (64B rows)
__device__ __forceinline__ uint32_t swz(int r, int c) {
    return (uint32_t)(r * 64 + ((c ^ ((r >> 1) & 3)) << 4));
}
// Swizzle for [rows][64 x 16-bit] tiles (128B rows)
__device__ __forceinline__ uint32_t swz128(int r, int c) {
    return (uint32_t)(r * 128 + ((c ^ (r & 7)) << 4));
}

#define SCALE 0.08838834764831845f

// ------------------------------------------------------------------
// fp32 -> fp16 conversion
// ------------------------------------------------------------------
__global__ __launch_bounds__(256)
void split16_kernel(const float4* __restrict__ src, int dst_sel, int n4)
{
    int i = blockIdx.x * 256 + threadIdx.x;
    if (i >= n4) return;
    __half* dst = (dst_sel == 0) ? g_x16 : (g_w16 + (size_t)(dst_sel - 1) * C_ * C_);
    float4 v = src[i];
    __half2* dp = (__half2*)dst;
    dp[2*i]   = __floats2half2_rn(v.x, v.y);
    dp[2*i+1] = __floats2half2_rn(v.z, v.w);
}

// ------------------------------------------------------------------
// fp16 HMMA GEMM. CTA tile 128x128, BK=64, 3 stages, 2 CTAs/SM.
// mode 1: g_x16 @ g_w16[z]^T -> Q/K fp32, V fp16 ([B,H,T,D])
// mode 0: g_y16 @ g_w16[3]^T -> Out fp32 [M, C]
// ------------------------------------------------------------------
#define G16_STAGE 32768             // A 16KB | B 16KB
#define G16_SMEM (1024 + 3*G16_STAGE)

__global__ __launch_bounds__(256, 2)
void gemm16(float* __restrict__ Out, int mode)
{
    extern __shared__ char dsm[];
    const int tid  = threadIdx.x;
    const int wid  = tid >> 5;
    const int lane = tid & 31;
    const int bn = blockIdx.x * 128;
    const int bm = blockIdx.y * 128;
    const int wz = blockIdx.z;

    const __half* A_g = (mode == 0) ? g_y16 : g_x16;
    const int widx = (mode == 0) ? 3 : wz;
    const __half* B_g = g_w16 + (size_t)widx * C_ * C_;

    const uint32_t base = (smem_u32(dsm) + 1023u) & ~1023u;

    auto load_stage = [&](int kt, int s) {
        const uint32_t sb = base + (uint32_t)s * G16_STAGE;
        const int kb = kt * 64;
        #pragma unroll
        for (int it = 0; it < 4; it++) {
            int idx = tid + it * 256;          // 0..1023
            int r = idx >> 3, c = idx & 7;
            uint32_t off = swz128(r, c);
            cp16(sb + off,         A_g + (size_t)(bm + r) * C_ + kb + c * 8);
            cp16(sb + 16384 + off, B_g + (size_t)(bn + r) * C_ + kb + c * 8);
        }
        cp_commit();
    };

    const int wm = (wid >> 1) * 32;
    const int wn = (wid & 1) * 64;
    const int arow = wm + (lane & 15);
    const int acol_base = (lane >> 4);
    const int brow = wn + (lane & 7) + ((lane & 16) >> 1);
    const int bcol_base = ((lane >> 3) & 1);

    float acc[2][8][4];
    #pragma unroll
    for (int i = 0; i < 2; i++)
        #pragma unroll
        for (int j = 0; j < 8; j++)
            #pragma unroll
            for (int q = 0; q < 4; q++) acc[i][j][q] = 0.0f;

    const int NK = C_ / 64;    // 32

    load_stage(0, 0);
    load_stage(1, 1);

    for (int c = 0; c < NK; c++) {
        __syncthreads();
        if (c + 2 < NK) load_stage(c + 2, (c + 2) % 3);
        else            cp_commit();
        asm volatile("cp.async.wait_group 2;" ::: "memory");
        __syncthreads();

        const uint32_t sA = base + (uint32_t)(c % 3) * G16_STAGE;
        const uint32_t sB = sA + 16384;

        #pragma unroll
        for (int ks = 0; ks < 4; ks++) {
            uint32_t ah[2][4];
            #pragma unroll
            for (int mt = 0; mt < 2; mt++)
                ldmx4(ah[mt], sA + swz128(arow + mt * 16, ks * 2 + acol_base));
            uint32_t bh[8][2];
            #pragma unroll
            for (int ng = 0; ng < 4; ng++) {
                uint32_t q[4];
                ldmx4(q, sB + swz128(brow + ng * 16, ks * 2 + bcol_base));
                bh[2*ng][0] = q[0]; bh[2*ng][1] = q[1];
                bh[2*ng+1][0] = q[2]; bh[2*ng+1][1] = q[3];
            }
            #pragma unroll
            for (int mt = 0; mt < 2; mt++)
                #pragma unroll
                for (int nt = 0; nt < 8; nt++)
                    mma16816h(acc[mt][nt], ah[mt], bh[nt]);
        }
    }

    float* qkv = (wz == 0) ? g_q : g_k;
    #pragma unroll
    for (int mt = 0; mt < 2; mt++) {
        const int row0 = bm + wm + mt * 16 + (lane >> 2);
        #pragma unroll
        for (int nt = 0; nt < 8; nt++) {
            const int col = bn + wn + nt * 8 + (lane & 3) * 2;
            #pragma unroll
            for (int half = 0; half < 2; half++) {
                const int row = row0 + half * 8;
                float y0 = acc[mt][nt][half * 2 + 0];
                float y1 = acc[mt][nt][half * 2 + 1];
                if (mode == 0) {
                    float2 v; v.x = y0; v.y = y1;
                    *(float2*)(Out + (size_t)row * C_ + col) = v;
                } else {
                    const int b = row >> 8, t = row & 255;
                    const int h = col >> 7, d0 = col & 127;
                    const size_t ix = (((size_t)b * H_ + h) * T_ + t) * D_ + d0;
                    if (wz < 2) {
                        float2 v; v.x = y0; v.y = y1;
                        *(float2*)(qkv + ix) = v;
                    } else {
                        *(__half2*)(g_v16 + ix) = __floats2half2_rn(y0, y1);
                    }
                }
            }
        }
    }
}

// ------------------------------------------------------------------
// RoPE tables + application (fp32 in, fp16 out)
// ------------------------------------------------------------------
__global__ void rope_table_kernel()
{
    int idx = blockIdx.x * blockDim.x + threadIdx.x;
    if (idx >= T_ * 64) return;
    int j = idx & 63;
    int t = idx >> 6;
    double inv = exp(-(double)j * (9.210340371976184 / 64.0));
    double th = (double)t * inv;
    g_cos[idx] = (float)cos(th);
    g_sin[idx] = (float)sin(th);
}

__global__ __launch_bounds__(256)
void rope_split_kernel()
{
    int idx = blockIdx.x * 256 + threadIdx.x;
    int j = idx & 63;
    int t = (idx >> 6) & 255;
    int rest = idx >> 14;
    int bh = rest & 511;
    int isK = rest >> 9;
    const float* src = (isK ? g_k : g_q) + ((size_t)bh * T_ + t) * D_ + j;
    float c = g_cos[t * 64 + j];
    float s = g_sin[t * 64 + j];
    float x0 = src[0], x1 = src[64];
    float r0 = x0 * c - x1 * s;
    float r1 = x1 * c + x0 * s;
    __half* dh = isK ? g_k16 : g_q16;
    const size_t bx = ((size_t)bh * T_ + t) * D_ + j;
    dh[bx]      = __float2half(r0);
    dh[bx + 64] = __float2half(r1);
}

// ------------------------------------------------------------------
// attn_qk: S = Q·K^T (fp16 single-term, causal tiles), S out fp16
// ------------------------------------------------------------------
#define QK_SMEM (1024 + 2*32768)

__global__ __launch_bounds__(256, 1)
void attn_qk()
{
    extern __shared__ char dsm[];
    const int tid  = threadIdx.x;
    const int wid  = tid >> 5;
    const int lane = tid & 31;
    const int pair = blockIdx.x;
    const int bh   = blockIdx.y;
    const int qt   = pair ? 1 : 0;
    const int kt   = (pair == 2) ? 1 : 0;

    const __half* Qg = g_q16 + ((size_t)bh * T_ + qt * 128) * D_;
    const __half* Kg = g_k16 + ((size_t)bh * T_ + kt * 128) * D_;

    const uint32_t base = (smem_u32(dsm) + 1023u) & ~1023u;

    // tiles chunked as [4][128][32 fp16], swizzled 64B rows
    #pragma unroll
    for (int it = 0; it < 8; it++) {
        int idx = tid + it * 256;            // 0..2047
        int r = idx >> 4, d16 = idx & 15;
        int c = d16 >> 2, ic = d16 & 3;
        uint32_t off = (uint32_t)c * 8192 + swz(r, ic);
        size_t g = (size_t)r * D_ + d16 * 8;
        cp16(base + off,         Qg + g);
        cp16(base + 32768 + off, Kg + g);
    }
    cp_commit();
    asm volatile("cp.async.wait_group 0;" ::: "memory");
    __syncthreads();

    const int wm = (wid >> 1) * 32;
    const int wn = (wid & 1) * 64;
    const int arow = wm + (lane & 15);
    const int acol_base = (lane >> 4);
    const int brow = wn + (lane & 7) + ((lane & 16) >> 1);
    const int bcol_base = ((lane >> 3) & 1);

    float acc[2][8][4];
    #pragma unroll
    for (int i = 0; i < 2; i++)
        #pragma unroll
        for (int j = 0; j < 8; j++)
            #pragma unroll
            for (int q = 0; q < 4; q++) acc[i][j][q] = 0.0f;

    #pragma unroll
    for (int c = 0; c < 4; c++) {
        const uint32_t sA = base + (uint32_t)c * 8192;
        const uint32_t sB = sA + 32768;
        #pragma unroll
        for (int ks = 0; ks < 2; ks++) {
            uint32_t ah[2][4];
            #pragma unroll
            for (int mt = 0; mt < 2; mt++)
                ldmx4(ah[mt], sA + swz(arow + mt * 16, ks * 2 + acol_base));
            uint32_t bh_[8][2];
            #pragma unroll
            for (int ng = 0; ng < 4; ng++) {
                uint32_t q[4];
                ldmx4(q, sB + swz(brow + ng * 16, ks * 2 + bcol_base));
                bh_[2*ng][0] = q[0]; bh_[2*ng][1] = q[1];
                bh_[2*ng+1][0] = q[2]; bh_[2*ng+1][1] = q[3];
            }
            #pragma unroll
            for (int mt = 0; mt < 2; mt++)
                #pragma unroll
                for (int nt = 0; nt < 8; nt++)
                    mma16816h(acc[mt][nt], ah[mt], bh_[nt]);
        }
    }

    // store S fp16
    #pragma unroll
    for (int mt = 0; mt < 2; mt++) {
        const int row0 = wm + mt * 16 + (lane >> 2);
        #pragma unroll
        for (int nt = 0; nt < 8; nt++) {
            const int col = wn + nt * 8 + (lane & 3) * 2;
            #pragma unroll
            for (int half = 0; half < 2; half++) {
                const int row = row0 + half * 8;
                *(__half2*)(g_s16 + ((size_t)bh * T_ + qt * 128 + row) * T_ + kt * 128 + col) =
                    __floats2half2_rn(acc[mt][nt][half * 2 + 0], acc[mt][nt][half * 2 + 1]);
            }
        }
    }
}

// ------------------------------------------------------------------
// softmax_p: masked row softmax (fp16 in) -> P fp16 (zero-padded)
// ------------------------------------------------------------------
__global__ __launch_bounds__(256)
void softmax_p()
{
    const int warp = threadIdx.x >> 5;
    const int lane = threadIdx.x & 31;
    const int row = blockIdx.x * 8 + warp;
    const int bh = row >> 8;
    const int q  = row & 255;
    const size_t rb = ((size_t)bh * T_ + q) * T_;
    const int W = (q < 128) ? 128 : 256;
    const int n = W >> 5;

    float e[8];
    float m = -1e30f;
    #pragma unroll
    for (int i = 0; i < 8; i++) {
        if (i >= n) break;
        int k = lane + 32 * i;
        float v = (k <= q) ? __half2float(g_s16[rb + k]) * SCALE : -1e30f;
        e[i] = v;
        m = fmaxf(m, v);
    }
    #pragma unroll
    for (int o = 16; o > 0; o >>= 1) m = fmaxf(m, __shfl_xor_sync(0xffffffffu, m, o));
    float sum = 0.f;
    #pragma unroll
    for (int i = 0; i < 8; i++) {
        if (i >= n) break;
        float x = __expf(e[i] - m);
        e[i] = x;
        sum += x;
    }
    #pragma unroll
    for (int o = 16; o > 0; o >>= 1) sum += __shfl_xor_sync(0xffffffffu, sum, o);
    const float inv = 1.0f / sum;
    #pragma unroll
    for (int i = 0; i < 8; i++) {
        if (i >= n) break;
        int k = lane + 32 * i;
        g_p16[rb + k] = __float2half(e[i] * inv);
    }
}

// ------------------------------------------------------------------
// attn_pv: Y = P @ V (fp16 single-term); epilogue -> g_y16 [B,T,C]
// ------------------------------------------------------------------
#define PV_STAGE 16896   // P 8192 | V 8704
#define PV_SMEM  (1024 + 2*PV_STAGE)

__global__ __launch_bounds__(256, 1)
void attn_pv()
{
    extern __shared__ char dsm[];
    const int tid  = threadIdx.x;
    const int wid  = tid >> 5;
    const int lane = tid & 31;
    const int qt = blockIdx.x;
    const int bh = blockIdx.y;

    const uint32_t base = (smem_u32(dsm) + 1023u) & ~1023u;
    const size_t prow = ((size_t)bh * T_ + qt * 128) * T_;
    const size_t vrow = (size_t)bh * T_ * D_;

    auto load_stage = [&](int kc, int s) {
        const uint32_t sb = base + (uint32_t)s * PV_STAGE;
        const int kb = kc * 32;
        #pragma unroll
        for (int it = 0; it < 2; it++) {       // P: 512 chunks
            int idx = tid + it * 256;
            int r = idx >> 2, ic = idx & 3;
            cp16(sb + swz(r, ic), g_p16 + prow + (size_t)r * T_ + kb + ic * 8);
        }
        #pragma unroll
        for (int it = 0; it < 2; it++) {       // V: 512 chunks, 272B pitch
            int idx = tid + it * 256;
            int r = idx >> 4, dc = idx & 15;
            cp16(sb + 8192 + (uint32_t)r * 272 + dc * 16,
                 g_v16 + vrow + (size_t)(kb + r) * D_ + dc * 8);
        }
        cp_commit();
    };

    const int wm = (wid >> 1) * 32;
    const int wn = (wid & 1) * 64;
    const int arow = wm + (lane & 15);
    const int acol_base = (lane >> 4);
    const int kl_part = ((lane >> 3) & 1) * 8 + (lane & 7);
    const int nblk = lane >> 4;

    float acc[2][8][4];
    #pragma unroll
    for (int i = 0; i < 2; i++)
        #pragma unroll
        for (int j = 0; j < 8; j++)
            #pragma unroll
            for (int q = 0; q < 4; q++) acc[i][j][q] = 0.0f;

    const int nc = (qt + 1) * 4;
    load_stage(0, 0);
    load_stage(1, 1);

    for (int kc = 0; kc < nc; kc++) {
        if (kc + 1 < nc) asm volatile("cp.async.wait_group 1;" ::: "memory");
        else             asm volatile("cp.async.wait_group 0;" ::: "memory");
        __syncthreads();

        const uint32_t sb = base + (uint32_t)(kc & 1) * PV_STAGE;
        const uint32_t sV = sb + 8192;

        #pragma unroll
        for (int ks = 0; ks < 2; ks++) {
            uint32_t ah[2][4];
            #pragma unroll
            for (int mt = 0; mt < 2; mt++)
                ldmx4(ah[mt], sb + swz(arow + mt * 16, ks * 2 + acol_base));
            uint32_t bh_[8][2];
            #pragma unroll
            for (int dp = 0; dp < 4; dp++) {
                const uint32_t addr = sV + (uint32_t)(ks * 16 + kl_part) * 272
                                    + (uint32_t)((wn >> 3) + dp * 2 + nblk) * 16;
                uint32_t q[4];
                ldmx4t(q, addr);
                bh_[2*dp][0] = q[0]; bh_[2*dp][1] = q[1];
                bh_[2*dp+1][0] = q[2]; bh_[2*dp+1][1] = q[3];
            }
            #pragma unroll
            for (int mt = 0; mt < 2; mt++)
                #pragma unroll
                for (int nt = 0; nt < 8; nt++)
                    mma16816h(acc[mt][nt], ah[mt], bh_[nt]);
        }
        __syncthreads();
        if (kc + 2 < nc) load_stage(kc + 2, kc & 1);
    }

    // epilogue: write y fp16 into [B,T,C]
    const int b = bh >> 4, h = bh & 15;
    #pragma unroll
    for (int mt = 0; mt < 2; mt++) {
        const int row0 = qt * 128 + wm + mt * 16 + (lane >> 2);
        #pragma unroll
        for (int nt = 0; nt < 8; nt++) {
            const int d = wn + nt * 8 + (lane & 3) * 2;
            #pragma unroll
            for (int half = 0; half < 2; half++) {
                const int t = row0 + half * 8;
                const size_t ix = ((size_t)b * T_ + t) * C_ + h * D_ + d;
                *(__half2*)(g_y16 + ix) =
                    __floats2half2_rn(acc[mt][nt][half * 2 + 0], acc[mt][nt][half * 2 + 1]);
            }
        }
    }
}

// ------------------------------------------------------------------
extern "C" void kernel_launch(void* const* d_in, const int* in_sizes, int n_in,
                              void* d_out, int out_size)
{
    const float* x  = (const float*)d_in[0];
    const float* wq = (const float*)d_in[1];
    const float* wk = (const float*)d_in[2];
    const float* wv = (const float*)d_in[3];
    const float* wo = (const float*)d_in[4];
    float* out = (float*)d_out;

    const int nx4 = M_TOT * C_ / 4;
    const int nw4 = C_ * C_ / 4;
    split16_kernel<<<(nx4 + 255)/256, 256>>>((const float4*)x,  0, nx4);
    split16_kernel<<<(nw4 + 255)/256, 256>>>((const float4*)wq, 1, nw4);
    split16_kernel<<<(nw4 + 255)/256, 256>>>((const float4*)wk, 2, nw4);
    split16_kernel<<<(nw4 + 255)/256, 256>>>((const float4*)wv, 3, nw4);
    split16_kernel<<<(nw4 + 255)/256, 256>>>((const float4*)wo, 4, nw4);

    cudaFuncSetAttribute(gemm16,  cudaFuncAttributeMaxDynamicSharedMemorySize, G16_SMEM);
    cudaFuncSetAttribute(attn_qk, cudaFuncAttributeMaxDynamicSharedMemorySize, QK_SMEM);
    cudaFuncSetAttribute(attn_pv, cudaFuncAttributeMaxDynamicSharedMemorySize, PV_SMEM);

    // QKV projections (fp16 HMMA, 2 CTAs/SM)
    gemm16<<<dim3(C_/128, M_TOT/128, 3), 256, G16_SMEM>>>(nullptr, 1);

    // RoPE -> fp16 Q,K
    rope_table_kernel<<<(T_*64 + 255)/256, 256>>>();
    rope_split_kernel<<<(2 * BH_ * T_ * 64) / 256, 256>>>();

    // Attention (fp16 single-term)
    attn_qk<<<dim3(3, BH_), 256, QK_SMEM>>>();
    softmax_p<<<(BH_ * T_) / 8, 256>>>();
    attn_pv<<<dim3(2, BH_), 256, PV_SMEM>>>();

    // Output projection
    gemm16<<<dim3(C_/128, M_TOT/128, 1), 256, G16_SMEM>>>(out, 0);
}

// round 7
// speedup vs baseline: 7.6207x; 1.0055x over previous
#include <cuda_runtime.h>
#include <cuda_bf16.h>
#include <cuda_fp16.h>
#include <cstdint>

#define B_  32
#define T_  256
#define C_  2048
#define H_  16
#define D_  128
#define M_TOT (B_*T_)     // 8192
#define BH_  (B_*H_)      // 512

// ------------------------------------------------------------------
// Device globals
// ------------------------------------------------------------------
__device__ float g_q[(size_t)BH_*T_*D_];
__device__ float g_k[(size_t)BH_*T_*D_];
__device__ float g_cos[T_*64];
__device__ float g_sin[T_*64];
__device__ __half g_x16[(size_t)M_TOT*C_];
__device__ __half g_w16[(size_t)4*C_*C_];
__device__ __half g_y16[(size_t)M_TOT*C_];
__device__ __half g_q16[(size_t)BH_*T_*D_];
__device__ __half g_k16[(size_t)BH_*T_*D_];
__device__ __half g_v16[(size_t)BH_*T_*D_];
__device__ __half g_s16[(size_t)BH_*T_*T_];
__device__ __half g_p16[(size_t)BH_*T_*T_];

// ------------------------------------------------------------------
// PTX helpers
// ------------------------------------------------------------------
__device__ __forceinline__ uint32_t smem_u32(const void* p) {
    uint32_t a;
    asm("{ .reg .u64 t; cvta.to.shared.u64 t, %1; cvt.u32.u64 %0, t; }" : "=r"(a) : "l"(p));
    return a;
}
__device__ __forceinline__ void cp16(uint32_t dst, const void* src) {
    asm volatile("cp.async.cg.shared.global [%0], [%1], 16;" :: "r"(dst), "l"(src));
}
__device__ __forceinline__ void cp_commit() {
    asm volatile("cp.async.commit_group;" ::: "memory");
}
__device__ __forceinline__ void ldmx4(uint32_t* r, uint32_t addr) {
    asm volatile("ldmatrix.sync.aligned.m8n8.x4.shared.b16 {%0,%1,%2,%3}, [%4];"
                 : "=r"(r[0]), "=r"(r[1]), "=r"(r[2]), "=r"(r[3]) : "r"(addr));
}
__device__ __forceinline__ void ldmx4t(uint32_t* r, uint32_t addr) {
    asm volatile("ldmatrix.sync.aligned.m8n8.x4.trans.shared.b16 {%0,%1,%2,%3}, [%4];"
                 : "=r"(r[0]), "=r"(r[1]), "=r"(r[2]), "=r"(r[3]) : "r"(addr));
}
__device__ __forceinline__ void mma16816h(float* d, const uint32_t* a, const uint32_t* b) {
    asm volatile(
        "mma.sync.aligned.m16n8k16.row.col.f32.f16.f16.f32 "
        "{%0,%1,%2,%3}, {%4,%5,%6,%7}, {%8,%9}, {%0,%1,%2,%3};"
        : "+f"(d[0]), "+f"(d[1]), "+f"(d[2]), "+f"(d[3])
        : "r"(a[0]), "r"(a[1]), "r"(a[2]), "r"(a[3]), "r"(b[0]), "r"(b[1]));
}
// Swizzle for [rows][32 x 16-bit] tiles (64B rows)
__device__ __forceinline__ uint32_t swz(int r, int c) {
    return (uint32_t)(r * 64 + ((c ^ ((r >> 1) & 3)) << 4));
}
// Swizzle for [rows][64 x 16-bit] tiles (128B rows)
__device__ __forceinline__ uint32_t swz128(int r, int c) {
    return (uint32_t)(r * 128 + ((c ^ (r & 7)) << 4));
}

#define SCALE 0.08838834764831845f

// ------------------------------------------------------------------
// fp32 -> fp16 conversion
// ------------------------------------------------------------------
__global__ __launch_bounds__(256)
void split16_kernel(const float4* __restrict__ src, int dst_sel, int n4)
{
    int i = blockIdx.x * 256 + threadIdx.x;
    if (i >= n4) return;
    __half* dst = (dst_sel == 0) ? g_x16 : (g_w16 + (size_t)(dst_sel - 1) * C_ * C_);
    float4 v = src[i];
    __half2* dp = (__half2*)dst;
    dp[2*i]   = __floats2half2_rn(v.x, v.y);
    dp[2*i+1] = __floats2half2_rn(v.z, v.w);
}

// ------------------------------------------------------------------
// fp16 HMMA GEMM. CTA tile 128x128, BK=64, 3 stages, 128 thr, 2 CTA/SM.
// 4 warps, 64x64 warp tiles (2x2) -> 128 B smem per MMA.
// mode 1: g_x16 @ g_w16[z]^T -> Q/K fp32, V fp16 ([B,H,T,D])
// mode 0: g_y16 @ g_w16[3]^T -> Out fp32 [M, C]
// ------------------------------------------------------------------
#define G16_STAGE 32768             // A 16KB | B 16KB
#define G16_SMEM (1024 + 3*G16_STAGE)

__global__ __launch_bounds__(128, 2)
void gemm16(float* __restrict__ Out, int mode)
{
    extern __shared__ char dsm[];
    const int tid  = threadIdx.x;
    const int wid  = tid >> 5;
    const int lane = tid & 31;
    const int bn = blockIdx.x * 128;
    const int bm = blockIdx.y * 128;
    const int wz = blockIdx.z;

    const __half* A_g = (mode == 0) ? g_y16 : g_x16;
    const int widx = (mode == 0) ? 3 : wz;
    const __half* B_g = g_w16 + (size_t)widx * C_ * C_;

    const uint32_t base = (smem_u32(dsm) + 1023u) & ~1023u;

    auto load_stage = [&](int kt, int s) {
        const uint32_t sb = base + (uint32_t)s * G16_STAGE;
        const int kb = kt * 64;
        #pragma unroll
        for (int it = 0; it < 8; it++) {
            int idx = tid + it * 128;          // 0..1023
            int r = idx >> 3, c = idx & 7;
            uint32_t off = swz128(r, c);
            cp16(sb + off,         A_g + (size_t)(bm + r) * C_ + kb + c * 8);
            cp16(sb + 16384 + off, B_g + (size_t)(bn + r) * C_ + kb + c * 8);
        }
        cp_commit();
    };

    // 2x2 warp grid of 64x64 tiles
    const int wm = (wid >> 1) * 64;
    const int wn = (wid & 1) * 64;
    const int arow = wm + (lane & 15);
    const int acol_base = (lane >> 4);
    const int brow = wn + (lane & 7) + ((lane & 16) >> 1);
    const int bcol_base = ((lane >> 3) & 1);

    float acc[4][8][4];
    #pragma unroll
    for (int i = 0; i < 4; i++)
        #pragma unroll
        for (int j = 0; j < 8; j++)
            #pragma unroll
            for (int q = 0; q < 4; q++) acc[i][j][q] = 0.0f;

    const int NK = C_ / 64;    // 32

    load_stage(0, 0);
    load_stage(1, 1);

    for (int c = 0; c < NK; c++) {
        __syncthreads();
        if (c + 2 < NK) load_stage(c + 2, (c + 2) % 3);
        else            cp_commit();
        asm volatile("cp.async.wait_group 2;" ::: "memory");
        __syncthreads();

        const uint32_t sA = base + (uint32_t)(c % 3) * G16_STAGE;
        const uint32_t sB = sA + 16384;

        #pragma unroll
        for (int ks = 0; ks < 4; ks++) {
            uint32_t ah[4][4];
            #pragma unroll
            for (int mt = 0; mt < 4; mt++)
                ldmx4(ah[mt], sA + swz128(arow + mt * 16, ks * 2 + acol_base));
            uint32_t bh[8][2];
            #pragma unroll
            for (int ng = 0; ng < 4; ng++) {
                uint32_t q[4];
                ldmx4(q, sB + swz128(brow + ng * 16, ks * 2 + bcol_base));
                bh[2*ng][0] = q[0]; bh[2*ng][1] = q[1];
                bh[2*ng+1][0] = q[2]; bh[2*ng+1][1] = q[3];
            }
            #pragma unroll
            for (int mt = 0; mt < 4; mt++)
                #pragma unroll
                for (int nt = 0; nt < 8; nt++)
                    mma16816h(acc[mt][nt], ah[mt], bh[nt]);
        }
    }

    float* qkv = (wz == 0) ? g_q : g_k;
    #pragma unroll
    for (int mt = 0; mt < 4; mt++) {
        const int row0 = bm + wm + mt * 16 + (lane >> 2);
        #pragma unroll
        for (int nt = 0; nt < 8; nt++) {
            const int col = bn + wn + nt * 8 + (lane & 3) * 2;
            #pragma unroll
            for (int half = 0; half < 2; half++) {
                const int row = row0 + half * 8;
                float y0 = acc[mt][nt][half * 2 + 0];
                float y1 = acc[mt][nt][half * 2 + 1];
                if (mode == 0) {
                    float2 v; v.x = y0; v.y = y1;
                    *(float2*)(Out + (size_t)row * C_ + col) = v;
                } else {
                    const int b = row >> 8, t = row & 255;
                    const int h = col >> 7, d0 = col & 127;
                    const size_t ix = (((size_t)b * H_ + h) * T_ + t) * D_ + d0;
                    if (wz < 2) {
                        float2 v; v.x = y0; v.y = y1;
                        *(float2*)(qkv + ix) = v;
                    } else {
                        *(__half2*)(g_v16 + ix) = __floats2half2_rn(y0, y1);
                    }
                }
            }
        }
    }
}

// ------------------------------------------------------------------
// RoPE tables + application (fp32 in, fp16 out)
// ------------------------------------------------------------------
__global__ void rope_table_kernel()
{
    int idx = blockIdx.x * blockDim.x + threadIdx.x;
    if (idx >= T_ * 64) return;
    int j = idx & 63;
    int t = idx >> 6;
    double inv = exp(-(double)j * (9.210340371976184 / 64.0));
    double th = (double)t * inv;
    g_cos[idx] = (float)cos(th);
    g_sin[idx] = (float)sin(th);
}

__global__ __launch_bounds__(256)
void rope_split_kernel()
{
    int idx = blockIdx.x * 256 + threadIdx.x;
    int j = idx & 63;
    int t = (idx >> 6) & 255;
    int rest = idx >> 14;
    int bh = rest & 511;
    int isK = rest >> 9;
    const float* src = (isK ? g_k : g_q) + ((size_t)bh * T_ + t) * D_ + j;
    float c = g_cos[t * 64 + j];
    float s = g_sin[t * 64 + j];
    float x0 = src[0], x1 = src[64];
    float r0 = x0 * c - x1 * s;
    float r1 = x1 * c + x0 * s;
    __half* dh = isK ? g_k16 : g_q16;
    const size_t bx = ((size_t)bh * T_ + t) * D_ + j;
    dh[bx]      = __float2half(r0);
    dh[bx + 64] = __float2half(r1);
}

// ------------------------------------------------------------------
// attn_qk: S = Q·K^T (fp16, causal tiles), S out fp16
// ------------------------------------------------------------------
#define QK_SMEM (1024 + 2*32768)

__global__ __launch_bounds__(256, 1)
void attn_qk()
{
    extern __shared__ char dsm[];
    const int tid  = threadIdx.x;
    const int wid  = tid >> 5;
    const int lane = tid & 31;
    const int pair = blockIdx.x;
    const int bh   = blockIdx.y;
    const int qt   = pair ? 1 : 0;
    const int kt   = (pair == 2) ? 1 : 0;

    const __half* Qg = g_q16 + ((size_t)bh * T_ + qt * 128) * D_;
    const __half* Kg = g_k16 + ((size_t)bh * T_ + kt * 128) * D_;

    const uint32_t base = (smem_u32(dsm) + 1023u) & ~1023u;

    #pragma unroll
    for (int it = 0; it < 8; it++) {
        int idx = tid + it * 256;
        int r = idx >> 4, d16 = idx & 15;
        int c = d16 >> 2, ic = d16 & 3;
        uint32_t off = (uint32_t)c * 8192 + swz(r, ic);
        size_t g = (size_t)r * D_ + d16 * 8;
        cp16(base + off,         Qg + g);
        cp16(base + 32768 + off, Kg + g);
    }
    cp_commit();
    asm volatile("cp.async.wait_group 0;" ::: "memory");
    __syncthreads();

    const int wm = (wid >> 1) * 32;
    const int wn = (wid & 1) * 64;
    const int arow = wm + (lane & 15);
    const int acol_base = (lane >> 4);
    const int brow = wn + (lane & 7) + ((lane & 16) >> 1);
    const int bcol_base = ((lane >> 3) & 1);

    float acc[2][8][4];
    #pragma unroll
    for (int i = 0; i < 2; i++)
        #pragma unroll
        for (int j = 0; j < 8; j++)
            #pragma unroll
            for (int q = 0; q < 4; q++) acc[i][j][q] = 0.0f;

    #pragma unroll
    for (int c = 0; c < 4; c++) {
        const uint32_t sA = base + (uint32_t)c * 8192;
        const uint32_t sB = sA + 32768;
        #pragma unroll
        for (int ks = 0; ks < 2; ks++) {
            uint32_t ah[2][4];
            #pragma unroll
            for (int mt = 0; mt < 2; mt++)
                ldmx4(ah[mt], sA + swz(arow + mt * 16, ks * 2 + acol_base));
            uint32_t bh_[8][2];
            #pragma unroll
            for (int ng = 0; ng < 4; ng++) {
                uint32_t q[4];
                ldmx4(q, sB + swz(brow + ng * 16, ks * 2 + bcol_base));
                bh_[2*ng][0] = q[0]; bh_[2*ng][1] = q[1];
                bh_[2*ng+1][0] = q[2]; bh_[2*ng+1][1] = q[3];
            }
            #pragma unroll
            for (int mt = 0; mt < 2; mt++)
                #pragma unroll
                for (int nt = 0; nt < 8; nt++)
                    mma16816h(acc[mt][nt], ah[mt], bh_[nt]);
        }
    }

    #pragma unroll
    for (int mt = 0; mt < 2; mt++) {
        const int row0 = wm + mt * 16 + (lane >> 2);
        #pragma unroll
        for (int nt = 0; nt < 8; nt++) {
            const int col = wn + nt * 8 + (lane & 3) * 2;
            #pragma unroll
            for (int half = 0; half < 2; half++) {
                const int row = row0 + half * 8;
                *(__half2*)(g_s16 + ((size_t)bh * T_ + qt * 128 + row) * T_ + kt * 128 + col) =
                    __floats2half2_rn(acc[mt][nt][half * 2 + 0], acc[mt][nt][half * 2 + 1]);
            }
        }
    }
}

// ------------------------------------------------------------------
// softmax_p: masked row softmax (fp16 in) -> P fp16 (zero-padded)
// ------------------------------------------------------------------
__global__ __launch_bounds__(256)
void softmax_p()
{
    const int warp = threadIdx.x >> 5;
    const int lane = threadIdx.x & 31;
    const int row = blockIdx.x * 8 + warp;
    const int bh = row >> 8;
    const int q  = row & 255;
    const size_t rb = ((size_t)bh * T_ + q) * T_;
    const int W = (q < 128) ? 128 : 256;
    const int n = W >> 5;

    float e[8];
    float m = -1e30f;
    #pragma unroll
    for (int i = 0; i < 8; i++) {
        if (i >= n) break;
        int k = lane + 32 * i;
        float v = (k <= q) ? __half2float(g_s16[rb + k]) * SCALE : -1e30f;
        e[i] = v;
        m = fmaxf(m, v);
    }
    #pragma unroll
    for (int o = 16; o > 0; o >>= 1) m = fmaxf(m, __shfl_xor_sync(0xffffffffu, m, o));
    float sum = 0.f;
    #pragma unroll
    for (int i = 0; i < 8; i++) {
        if (i >= n) break;
        float x = __expf(e[i] - m);
        e[i] = x;
        sum += x;
    }
    #pragma unroll
    for (int o = 16; o > 0; o >>= 1) sum += __shfl_xor_sync(0xffffffffu, sum, o);
    const float inv = 1.0f / sum;
    #pragma unroll
    for (int i = 0; i < 8; i++) {
        if (i >= n) break;
        int k = lane + 32 * i;
        g_p16[rb + k] = __float2half(e[i] * inv);
    }
}

// ------------------------------------------------------------------
// attn_pv: Y = P @ V (fp16); epilogue -> g_y16 [B,T,C]
// ------------------------------------------------------------------
#define PV_STAGE 16896   // P 8192 | V 8704
#define PV_SMEM  (1024 + 2*PV_STAGE)

__global__ __launch_bounds__(256, 1)
void attn_pv()
{
    extern __shared__ char dsm[];
    const int tid  = threadIdx.x;
    const int wid  = tid >> 5;
    const int lane = tid & 31;
    const int qt = blockIdx.x;
    const int bh = blockIdx.y;

    const uint32_t base = (smem_u32(dsm) + 1023u) & ~1023u;
    const size_t prow = ((size_t)bh * T_ + qt * 128) * T_;
    const size_t vrow = (size_t)bh * T_ * D_;

    auto load_stage = [&](int kc, int s) {
        const uint32_t sb = base + (uint32_t)s * PV_STAGE;
        const int kb = kc * 32;
        #pragma unroll
        for (int it = 0; it < 2; it++) {
            int idx = tid + it * 256;
            int r = idx >> 2, ic = idx & 3;
            cp16(sb + swz(r, ic), g_p16 + prow + (size_t)r * T_ + kb + ic * 8);
        }
        #pragma unroll
        for (int it = 0; it < 2; it++) {
            int idx = tid + it * 256;
            int r = idx >> 4, dc = idx & 15;
            cp16(sb + 8192 + (uint32_t)r * 272 + dc * 16,
                 g_v16 + vrow + (size_t)(kb + r) * D_ + dc * 8);
        }
        cp_commit();
    };

    const int wm = (wid >> 1) * 32;
    const int wn = (wid & 1) * 64;
    const int arow = wm + (lane & 15);
    const int acol_base = (lane >> 4);
    const int kl_part = ((lane >> 3) & 1) * 8 + (lane & 7);
    const int nblk = lane >> 4;

    float acc[2][8][4];
    #pragma unroll
    for (int i = 0; i < 2; i++)
        #pragma unroll
        for (int j = 0; j < 8; j++)
            #pragma unroll
            for (int q = 0; q < 4; q++) acc[i][j][q] = 0.0f;

    const int nc = (qt + 1) * 4;
    load_stage(0, 0);
    load_stage(1, 1);

    for (int kc = 0; kc < nc; kc++) {
        if (kc + 1 < nc) asm volatile("cp.async.wait_group 1;" ::: "memory");
        else             asm volatile("cp.async.wait_group 0;" ::: "memory");
        __syncthreads();

        const uint32_t sb = base + (uint32_t)(kc & 1) * PV_STAGE;
        const uint32_t sV = sb + 8192;

        #pragma unroll
        for (int ks = 0; ks < 2; ks++) {
            uint32_t ah[2][4];
            #pragma unroll
            for (int mt = 0; mt < 2; mt++)
                ldmx4(ah[mt], sb + swz(arow + mt * 16, ks * 2 + acol_base));
            uint32_t bh_[8][2];
            #pragma unroll
            for (int dp = 0; dp < 4; dp++) {
                const uint32_t addr = sV + (uint32_t)(ks * 16 + kl_part) * 272
                                    + (uint32_t)((wn >> 3) + dp * 2 + nblk) * 16;
                uint32_t q[4];
                ldmx4t(q, addr);
                bh_[2*dp][0] = q[0]; bh_[2*dp][1] = q[1];
                bh_[2*dp+1][0] = q[2]; bh_[2*dp+1][1] = q[3];
            }
            #pragma unroll
            for (int mt = 0; mt < 2; mt++)
                #pragma unroll
                for (int nt = 0; nt < 8; nt++)
                    mma16816h(acc[mt][nt], ah[mt], bh_[nt]);
        }
        __syncthreads();
        if (kc + 2 < nc) load_stage(kc + 2, kc & 1);
    }

    const int b = bh >> 4, h = bh & 15;
    #pragma unroll
    for (int mt = 0; mt < 2; mt++) {
        const int row0 = qt * 128 + wm + mt * 16 + (lane >> 2);
        #pragma unroll
        for (int nt = 0; nt < 8; nt++) {
            const int d = wn + nt * 8 + (lane & 3) * 2;
            #pragma unroll
            for (int half = 0; half < 2; half++) {
                const int t = row0 + half * 8;
                const size_t ix = ((size_t)b * T_ + t) * C_ + h * D_ + d;
                *(__half2*)(g_y16 + ix) =
                    __floats2half2_rn(acc[mt][nt][half * 2 + 0], acc[mt][nt][half * 2 + 1]);
            }
        }
    }
}

// ------------------------------------------------------------------
extern "C" void kernel_launch(void* const* d_in, const int* in_sizes, int n_in,
                              void* d_out, int out_size)
{
    const float* x  = (const float*)d_in[0];
    const float* wq = (const float*)d_in[1];
    const float* wk = (const float*)d_in[2];
    const float* wv = (const float*)d_in[3];
    const float* wo = (const float*)d_in[4];
    float* out = (float*)d_out;

    const int nx4 = M_TOT * C_ / 4;
    const int nw4 = C_ * C_ / 4;
    split16_kernel<<<(nx4 + 255)/256, 256>>>((const float4*)x,  0, nx4);
    split16_kernel<<<(nw4 + 255)/256, 256>>>((const float4*)wq, 1, nw4);
    split16_kernel<<<(nw4 + 255)/256, 256>>>((const float4*)wk, 2, nw4);
    split16_kernel<<<(nw4 + 255)/256, 256>>>((const float4*)wv, 3, nw4);
    split16_kernel<<<(nw4 + 255)/256, 256>>>((const float4*)wo, 4, nw4);

    cudaFuncSetAttribute(gemm16,  cudaFuncAttributeMaxDynamicSharedMemorySize, G16_SMEM);
    cudaFuncSetAttribute(attn_qk, cudaFuncAttributeMaxDynamicSharedMemorySize, QK_SMEM);
    cudaFuncSetAttribute(attn_pv, cudaFuncAttributeMaxDynamicSharedMemorySize, PV_SMEM);

    // QKV projections (fp16 HMMA, 4 warps / 64x64 tiles, 2 CTAs/SM)
    gemm16<<<dim3(C_/128, M_TOT/128, 3), 128, G16_SMEM>>>(nullptr, 1);

    // RoPE -> fp16 Q,K
    rope_table_kernel<<<(T_*64 + 255)/256, 256>>>();
    rope_split_kernel<<<(2 * BH_ * T_ * 64) / 256, 256>>>();

    // Attention
    attn_qk<<<dim3(3, BH_), 256, QK_SMEM>>>();
    softmax_p<<<(BH_ * T_) / 8, 256>>>();
    attn_pv<<<dim3(2, BH_), 256, PV_SMEM>>>();

    // Output projection
    gemm16<<<dim3(C_/128, M_TOT/128, 1), 128, G16_SMEM>>>(out, 0);
}